// round 3
// baseline (speedup 1.0000x reference)
#include <cuda_runtime.h>
#include <math.h>
#include <stdint.h>

// ---------------------------------------------------------------------------
// Two-layer tanh RNN.  SEQ=512, BATCH=64, IN=HD=1024, fp32.
//   h1(t) = tanh(x(t)@Wi0^T + bi0 + h1(t-1)@Wh0^T + bh0)
//   h2(t) = tanh(h1(t)@Wi1^T + bi1 + h2(t-1)@Wh1^T + bh1)
// Output: outputs[512,64,1024] (h2 per step) ++ h_final[2,64,1024].
//
// Structure:
//   1) reset kernel      : zero grid-barrier counter + initial hidden state
//   2) precompute kernel : P = x@Wi0^T + bi0 + bh0  (big parallel fp32 GEMM)
//   3) persistent kernel : 512 steps, 128 CTAs (one wave), weights in SMEM,
//                          hardened grid sync between phases.
// ---------------------------------------------------------------------------

#define SEQ   512
#define BATCH 64
#define HD    1024
#define MTOT  (SEQ*BATCH)                    // 32768
#define OUT_MAIN ((size_t)SEQ*BATCH*HD)      // 33554432

#define NCTA 128
#define TPB  256
#define NSL  8                               // output columns per CTA

// dynamic smem layout (in floats)
#define STG_ROW   68                         // 64 + pad (bank-conflict avoidance)
#define STG_SZ    (64*STG_ROW)               // one stage buffer: 64 rows x 64 k
#define SW_FLOATS (3*NSL*HD)                 // 24576
#define STG_OFF   SW_FLOATS
#define SREDA_OFF (STG_OFF + 4*STG_SZ)       // 24576 + 17408 = 41984
#define SREDB_OFF (SREDA_OFF + 512)
#define SMEM_FLOATS (SREDB_OFF + 512)        // 43008
#define SMEM_BYTES  (SMEM_FLOATS*4)          // 172032 bytes

// scratch (device globals: no allocations allowed)
__device__ float g_P[33554432];              // 128 MB precomputed input term
__device__ float g_h1[2][BATCH*HD];
__device__ float g_h2[2][BATCH*HD];
__device__ unsigned g_count;

// ---------------------------------------------------------------------------
// 1) reset: zero the barrier counter and initial hidden states (per launch,
//    so graph replays are deterministic).
// ---------------------------------------------------------------------------
__global__ void rnn_reset_kernel() {
    unsigned idx = blockIdx.x * blockDim.x + threadIdx.x;
    if (idx == 0) g_count = 0u;
    if (idx < BATCH*HD) {
        g_h1[0][idx] = 0.f;
        g_h2[0][idx] = 0.f;
    }
}

// ---------------------------------------------------------------------------
// 2) precompute: P[m][n] = sum_k X[m][k]*Wi0[n][k] + bi0[n] + bh0[n]
//    Classic 64x64 tile, BK=16, 256 threads, 4x4 register tile.
// ---------------------------------------------------------------------------
__global__ __launch_bounds__(256)
void rnn_precompute_kernel(const float* __restrict__ X,
                           const float* __restrict__ Wi0,
                           const float* __restrict__ bi0,
                           const float* __restrict__ bh0)
{
    __shared__ float As[16][68];
    __shared__ float Bs[16][68];

    const int bm = blockIdx.y * 64;
    const int bn = blockIdx.x * 64;
    const int tid = threadIdx.x;
    const int ty = tid >> 4, tx = tid & 15;
    const int m0 = ty * 4, n0 = tx * 4;
    const int lm = tid >> 2;
    const int lk = (tid & 3) * 4;

    const float* Ap = X   + (size_t)(bm + lm) * HD + lk;
    const float* Bp = Wi0 + (size_t)(bn + lm) * HD + lk;

    float4 a = *(const float4*)Ap;
    float4 b = *(const float4*)Bp;

    float acc[4][4];
#pragma unroll
    for (int i = 0; i < 4; i++)
#pragma unroll
        for (int j = 0; j < 4; j++) acc[i][j] = 0.f;

    for (int k0 = 0; k0 < HD; k0 += 16) {
        __syncthreads();
        As[lk+0][lm] = a.x; As[lk+1][lm] = a.y; As[lk+2][lm] = a.z; As[lk+3][lm] = a.w;
        Bs[lk+0][lm] = b.x; Bs[lk+1][lm] = b.y; Bs[lk+2][lm] = b.z; Bs[lk+3][lm] = b.w;
        __syncthreads();
        if (k0 + 16 < HD) {
            a = *(const float4*)(Ap + k0 + 16);
            b = *(const float4*)(Bp + k0 + 16);
        }
#pragma unroll
        for (int k = 0; k < 16; k++) {
            const float4 av = *(const float4*)&As[k][m0];
            const float4 bv = *(const float4*)&Bs[k][n0];
            float am[4] = {av.x, av.y, av.z, av.w};
            float bb[4] = {bv.x, bv.y, bv.z, bv.w};
#pragma unroll
            for (int i = 0; i < 4; i++)
#pragma unroll
                for (int j = 0; j < 4; j++) acc[i][j] += am[i] * bb[j];
        }
    }

    const int gn = bn + n0;
    float b0[4];
#pragma unroll
    for (int j = 0; j < 4; j++) b0[j] = bi0[gn + j] + bh0[gn + j];
#pragma unroll
    for (int i = 0; i < 4; i++) {
        float4 r;
        r.x = acc[i][0] + b0[0];
        r.y = acc[i][1] + b0[1];
        r.z = acc[i][2] + b0[2];
        r.w = acc[i][3] + b0[3];
        *(float4*)&g_P[(size_t)(bm + m0 + i) * HD + gn] = r;
    }
}

// ---------------------------------------------------------------------------
// 3) persistent recurrent kernel
// ---------------------------------------------------------------------------
__device__ __forceinline__ void barx(int id) {
    asm volatile("bar.sync %0, %1;" :: "r"(id), "r"(128) : "memory");
}

// Canonical cooperative-style grid barrier:
//   every thread fences its own writes -> block barrier -> thread 0 arrives
//   (release via fence+atomic) and spins with backoff -> fence -> barrier.
__device__ __forceinline__ void grid_sync(unsigned& target) {
    __threadfence();                 // order THIS thread's h-state stores
    __syncthreads();
    target += NCTA;
    if (threadIdx.x == 0) {
        atomicAdd(&g_count, 1u);
        unsigned v;
        do {
            v = *((volatile unsigned*)&g_count);
            if (v >= target) break;
            __nanosleep(64);
        } while (true);
        __threadfence();             // acquire: make peers' stores visible
    }
    __syncthreads();
}

// One half (128 threads) accumulates acc[4] = sum over [kstart, kstart+klen)
// of hsrc[b][k] * W[n][k] for its 4 output columns. h is staged coalesced
// into double-buffered SMEM (named barrier per half), weights come from SMEM.
__device__ __forceinline__ void accum_half(
    float acc[4], const float* __restrict__ hsrc, const float* __restrict__ sW,
    int kstart, int klen, float* stg0, float* stg1,
    int barid, int ht, int b, int nq)
{
    acc[0] = acc[1] = acc[2] = acc[3] = 0.f;
    const int rbase = ht >> 4;          // 0..7
    const int kk    = (ht & 15) << 2;   // 0..60

    // prefetch chunk 0 into stg0
#pragma unroll
    for (int p = 0; p < 8; p++) {
        const int row = (p << 3) + rbase;
        float4 v = __ldcg(reinterpret_cast<const float4*>(
            hsrc + (size_t)row * HD + kstart + kk));
        *reinterpret_cast<float4*>(stg0 + row * STG_ROW + kk) = v;
    }

    const int nchunk = klen >> 6;
    for (int c = 0; c < nchunk; c++) {
        float* cur = (c & 1) ? stg1 : stg0;
        float* nxt = (c & 1) ? stg0 : stg1;
        barx(barid);                    // drains STS into cur; frees nxt
        if (c + 1 < nchunk) {
            const int kp = kstart + ((c + 1) << 6);
#pragma unroll
            for (int p = 0; p < 8; p++) {
                const int row = (p << 3) + rbase;
                float4 v = __ldcg(reinterpret_cast<const float4*>(
                    hsrc + (size_t)row * HD + kp + kk));
                *reinterpret_cast<float4*>(nxt + row * STG_ROW + kk) = v;
            }
        }
        const int kof = kstart + (c << 6);
        const float* hrow = cur + b * STG_ROW;
        const float* w0 = sW + (nq * 4 + 0) * HD + kof;
        const float* w1 = w0 + HD;
        const float* w2 = w1 + HD;
        const float* w3 = w2 + HD;
#pragma unroll
        for (int k4 = 0; k4 < 16; k4++) {
            const float4 hv = *(const float4*)(hrow + (k4 << 2));
            const float4 a0 = *(const float4*)(w0 + (k4 << 2));
            acc[0] += hv.x*a0.x + hv.y*a0.y + hv.z*a0.z + hv.w*a0.w;
            const float4 a1 = *(const float4*)(w1 + (k4 << 2));
            acc[1] += hv.x*a1.x + hv.y*a1.y + hv.z*a1.z + hv.w*a1.w;
            const float4 a2 = *(const float4*)(w2 + (k4 << 2));
            acc[2] += hv.x*a2.x + hv.y*a2.y + hv.z*a2.z + hv.w*a2.w;
            const float4 a3 = *(const float4*)(w3 + (k4 << 2));
            acc[3] += hv.x*a3.x + hv.y*a3.y + hv.z*a3.z + hv.w*a3.w;
        }
    }
}

__global__ __launch_bounds__(TPB)
void rnn_recurrent_kernel(const float* __restrict__ Wh0,
                          const float* __restrict__ Wi1,
                          const float* __restrict__ Wh1,
                          const float* __restrict__ bi1,
                          const float* __restrict__ bh1,
                          float* __restrict__ out,
                          int write_final)
{
    extern __shared__ float smem[];
    float* sWh0  = smem;
    float* sWi1  = smem + NSL*HD;
    float* sWh1  = smem + 2*NSL*HD;
    float* stg   = smem + STG_OFF;
    float* sredA = smem + SREDA_OFF;
    float* sredB = smem + SREDB_OFF;

    const int tid   = threadIdx.x;
    const int nbase = blockIdx.x * NSL;
    const int half  = tid >> 7;     // 0 or 1 (warps 0-3 / 4-7)
    const int ht    = tid & 127;
    const int b     = ht >> 1;      // batch row 0..63
    const int nq    = ht & 1;       // which 4-column quad
    const int barid = half + 1;     // named barriers 1 / 2
    float* stg0 = stg + (half * 2 + 0) * STG_SZ;
    float* stg1 = stg + (half * 2 + 1) * STG_SZ;

    // load the CTA's 8-column weight slices into SMEM (resident all 512 steps)
    {
        const float* w0 = Wh0 + (size_t)nbase * HD;
        const float* w1 = Wi1 + (size_t)nbase * HD;
        const float* w2 = Wh1 + (size_t)nbase * HD;
        for (int i = tid * 4; i < NSL * HD; i += TPB * 4) {
            *(float4*)(sWh0 + i) = *(const float4*)(w0 + i);
            *(float4*)(sWi1 + i) = *(const float4*)(w1 + i);
            *(float4*)(sWh1 + i) = *(const float4*)(w2 + i);
        }
    }

    // per-thread epilogue constants (2 outputs each)
    float bias2[2];
    int eb_[2], en_[2];
#pragma unroll
    for (int e = 0; e < 2; e++) {
        const int oo = tid * 2 + e;
        eb_[e] = oo >> 3;
        en_[e] = oo & 7;
        bias2[e] = bi1[nbase + en_[e]] + bh1[nbase + en_[e]];
    }
    __syncthreads();

    unsigned target = 0;
    for (int t = 0; t < SEQ; t++) {
        const int rb = t & 1, wb = rb ^ 1;
        const float* h1p = g_h1[rb];
        float*       h1n = g_h1[wb];
        const float* h2p = g_h2[rb];
        float*       h2n = g_h2[wb];
        const int last = (t == SEQ - 1);

        float acc[4];

        // ---------- Layer 1: h1 = tanh(P(t) + h1p @ Wh0^T) ----------
        // half 0: k in [0,512), half 1: k in [512,1024)
        accum_half(acc, h1p, sWh0, half * 512, 512, stg0, stg1, barid, ht, b, nq);
        {
            float* sr = half ? sredB : sredA;
            const int o = b * NSL + nq * 4;
            sr[o+0] = acc[0]; sr[o+1] = acc[1]; sr[o+2] = acc[2]; sr[o+3] = acc[3];
        }
        __syncthreads();
        {
            const float* Pt = g_P + (size_t)t * BATCH * HD;
#pragma unroll
            for (int e = 0; e < 2; e++) {
                const int oo = tid * 2 + e;
                float v = sredA[oo] + sredB[oo]
                        + Pt[(size_t)eb_[e] * HD + nbase + en_[e]];
                v = tanhf(v);
                __stcg(h1n + (size_t)eb_[e] * HD + nbase + en_[e], v);
                if (write_final && last)
                    out[OUT_MAIN + (size_t)eb_[e] * HD + nbase + en_[e]] = v;
            }
        }
        grid_sync(target);

        // ---------- Layer 2: h2 = tanh(h1 @ Wi1^T + h2p @ Wh1^T + b) ----------
        // half 0: Wi1 with fresh h1 (full K); half 1: Wh1 with h2p (full K)
        accum_half(acc, half ? h2p : h1n, half ? sWh1 : sWi1,
                   0, HD, stg0, stg1, barid, ht, b, nq);
        {
            float* sr = half ? sredB : sredA;
            const int o = b * NSL + nq * 4;
            sr[o+0] = acc[0]; sr[o+1] = acc[1]; sr[o+2] = acc[2]; sr[o+3] = acc[3];
        }
        __syncthreads();
        {
#pragma unroll
            for (int e = 0; e < 2; e++) {
                const int oo = tid * 2 + e;
                float v = sredA[oo] + sredB[oo] + bias2[e];
                v = tanhf(v);
                __stcg(h2n + (size_t)eb_[e] * HD + nbase + en_[e], v);
                out[(size_t)t * BATCH * HD + (size_t)eb_[e] * HD + nbase + en_[e]] = v;
                if (write_final && last)
                    out[OUT_MAIN + (size_t)BATCH * HD
                        + (size_t)eb_[e] * HD + nbase + en_[e]] = v;
            }
        }
        grid_sync(target);
    }
}

// ---------------------------------------------------------------------------
// launcher
// ---------------------------------------------------------------------------
extern "C" void kernel_launch(void* const* d_in, const int* in_sizes, int n_in,
                              void* d_out, int out_size) {
    const float* x   = (const float*)d_in[0];
    const float* Wi0 = (const float*)d_in[1];
    const float* bi0 = (const float*)d_in[2];
    const float* Wh0 = (const float*)d_in[3];
    const float* bh0 = (const float*)d_in[4];
    const float* Wi1 = (const float*)d_in[5];
    const float* bi1 = (const float*)d_in[6];
    const float* Wh1 = (const float*)d_in[7];
    const float* bh1 = (const float*)d_in[8];
    float* out = (float*)d_out;

    const int write_final =
        ((size_t)out_size >= OUT_MAIN + (size_t)2 * BATCH * HD) ? 1 : 0;

    // idempotent, host-side only; safe under graph capture
    cudaFuncSetAttribute(rnn_recurrent_kernel,
                         cudaFuncAttributeMaxDynamicSharedMemorySize, SMEM_BYTES);

    rnn_reset_kernel<<<(BATCH*HD + 255) / 256, 256>>>();
    rnn_precompute_kernel<<<dim3(HD/64, MTOT/64), 256>>>(x, Wi0, bi0, bh0);
    rnn_recurrent_kernel<<<NCTA, TPB, SMEM_BYTES>>>(Wh0, Wi1, Wh1, bi1, bh1,
                                                    out, write_final);
}

// round 4
// speedup vs baseline: 1.4572x; 1.4572x over previous
#include <cuda_runtime.h>
#include <math.h>
#include <stdint.h>

// ---------------------------------------------------------------------------
// Two-layer tanh RNN.  SEQ=512, BATCH=64, IN=HD=1024, fp32.
//   h1(t) = tanh(x(t)@Wi0^T + bi0 + h1(t-1)@Wh0^T + bh0)
//   h2(t) = tanh(h1(t)@Wi1^T + bi1 + h2(t-1)@Wh1^T + bh1)
// Output: outputs[512,64,1024] ++ h_final[2,64,1024].
//
//   1) reset      : zero barrier counters + initial hidden state
//   2) precompute : P = x@Wi0^T + bi0 + bh0 (unchanged, known-good)
//   3) recurrent  : persistent, 128 CTAs x 512 thr, weights in SMEM,
//                   cp.async h staging, split arrive/wait grid sync.
// ---------------------------------------------------------------------------

#define SEQ   512
#define BATCH 64
#define HD    1024
#define MTOT  (SEQ*BATCH)
#define OUT_MAIN ((size_t)SEQ*BATCH*HD)

#define NCTA 128
#define TPB  512
#define NSL  8                         // output columns per CTA

// smem layout (floats)
#define WROW   1028                    // 1024 + 4 pad: kills nq0/nq1 bank conflict
#define SW_FLOATS (3*NSL*WROW)         // 24672
#define STG_OFF   SW_FLOATS
#define STG_BUF   2048                 // one chunk: 64 rows x 32 k
#define RED1_OFF  (STG_OFF + 8*STG_BUF)    // 24672+16384 = 41056
#define RED2_OFF  (RED1_OFF + 2048)
#define SMEM_FLOATS (RED2_OFF + 2048)      // 45152
#define SMEM_BYTES  (SMEM_FLOATS*4)        // 180608

__device__ float g_P[33554432];        // 128 MB precomputed input term
__device__ float g_h1[2][BATCH*HD];
__device__ float g_h2[2][BATCH*HD];
__device__ unsigned g_c1, g_c2;

// ---------------------------------------------------------------------------
__global__ void rnn_reset_kernel() {
    unsigned idx = blockIdx.x * blockDim.x + threadIdx.x;
    if (idx == 0) { g_c1 = 0u; g_c2 = 0u; }
    if (idx < BATCH*HD) {
        g_h1[0][idx] = 0.f;
        g_h2[0][idx] = 0.f;
    }
}

// ---------------------------------------------------------------------------
// precompute (unchanged from passing R3 kernel)
// ---------------------------------------------------------------------------
__global__ __launch_bounds__(256)
void rnn_precompute_kernel(const float* __restrict__ X,
                           const float* __restrict__ Wi0,
                           const float* __restrict__ bi0,
                           const float* __restrict__ bh0)
{
    __shared__ float As[16][68];
    __shared__ float Bs[16][68];

    const int bm = blockIdx.y * 64;
    const int bn = blockIdx.x * 64;
    const int tid = threadIdx.x;
    const int ty = tid >> 4, tx = tid & 15;
    const int m0 = ty * 4, n0 = tx * 4;
    const int lm = tid >> 2;
    const int lk = (tid & 3) * 4;

    const float* Ap = X   + (size_t)(bm + lm) * HD + lk;
    const float* Bp = Wi0 + (size_t)(bn + lm) * HD + lk;

    float4 a = *(const float4*)Ap;
    float4 b = *(const float4*)Bp;

    float acc[4][4];
#pragma unroll
    for (int i = 0; i < 4; i++)
#pragma unroll
        for (int j = 0; j < 4; j++) acc[i][j] = 0.f;

    for (int k0 = 0; k0 < HD; k0 += 16) {
        __syncthreads();
        As[lk+0][lm] = a.x; As[lk+1][lm] = a.y; As[lk+2][lm] = a.z; As[lk+3][lm] = a.w;
        Bs[lk+0][lm] = b.x; Bs[lk+1][lm] = b.y; Bs[lk+2][lm] = b.z; Bs[lk+3][lm] = b.w;
        __syncthreads();
        if (k0 + 16 < HD) {
            a = *(const float4*)(Ap + k0 + 16);
            b = *(const float4*)(Bp + k0 + 16);
        }
#pragma unroll
        for (int k = 0; k < 16; k++) {
            const float4 av = *(const float4*)&As[k][m0];
            const float4 bv = *(const float4*)&Bs[k][n0];
            float am[4] = {av.x, av.y, av.z, av.w};
            float bb[4] = {bv.x, bv.y, bv.z, bv.w};
#pragma unroll
            for (int i = 0; i < 4; i++)
#pragma unroll
                for (int j = 0; j < 4; j++) acc[i][j] += am[i] * bb[j];
        }
    }

    const int gn = bn + n0;
    float b0[4];
#pragma unroll
    for (int j = 0; j < 4; j++) b0[j] = bi0[gn + j] + bh0[gn + j];
#pragma unroll
    for (int i = 0; i < 4; i++) {
        float4 r;
        r.x = acc[i][0] + b0[0];
        r.y = acc[i][1] + b0[1];
        r.z = acc[i][2] + b0[2];
        r.w = acc[i][3] + b0[3];
        *(float4*)&g_P[(size_t)(bm + m0 + i) * HD + gn] = r;
    }
}

// ---------------------------------------------------------------------------
// recurrent kernel helpers
// ---------------------------------------------------------------------------
__device__ __forceinline__ void barx(int id) {
    asm volatile("bar.sync %0, %1;" :: "r"(id), "r"(128) : "memory");
}

// split grid barrier: arrive once per CTA, wait for target arrivals
__device__ __forceinline__ void grid_arrive(unsigned* c) {
    __threadfence();
    __syncthreads();
    if (threadIdx.x == 0) atomicAdd(c, 1u);
}
__device__ __forceinline__ void grid_wait(unsigned* c, unsigned target) {
    if (threadIdx.x == 0) {
        while (*((volatile unsigned*)c) < target) __nanosleep(32);
        __threadfence();
    }
    __syncthreads();
}

__device__ __forceinline__ unsigned sptr(const void* p) {
    return (unsigned)__cvta_generic_to_shared(p);
}
#define CP_COMMIT() asm volatile("cp.async.commit_group;" ::: "memory")
#define CP_WAIT1()  asm volatile("cp.async.wait_group 1;" ::: "memory")

// stage one 64x32 chunk of h (rows 0..63, k in [k0,k0+32)) into swizzled buf.
// thread (row=b, j): 4x cp.async.cg 16B. dst word = row*32 + ((k4+row)&7)*4.
__device__ __forceinline__ void stage32(float* buf, const float* src,
                                        int k0, int row, int j) {
    const float* s = src + (size_t)row * HD + k0 + j * 16;
    unsigned d = sptr(buf + row * 32);
#pragma unroll
    for (int i = 0; i < 4; i++) {
        const int k4 = j * 4 + i;
        unsigned dd = d + (((k4 + row) & 7) << 4);
        asm volatile("cp.async.cg.shared.global [%0], [%1], 16;"
                     :: "r"(dd), "l"(s + i * 4) : "memory");
    }
}

// 8 k4-iterations over one staged chunk; weights from SMEM (broadcast).
__device__ __forceinline__ void chunk_fma(float acc[4], const float* buf,
                                          const float* w0, int b) {
    const float* hrow = buf + b * 32;
    const float* w1 = w0 + WROW;
    const float* w2 = w0 + 2 * WROW;
    const float* w3 = w0 + 3 * WROW;
#pragma unroll
    for (int k4 = 0; k4 < 8; k4++) {
        const float4 hv = *(const float4*)(hrow + (((k4 + b) & 7) << 2));
        const float4 a0 = *(const float4*)(w0 + (k4 << 2));
        acc[0] += hv.x*a0.x + hv.y*a0.y + hv.z*a0.z + hv.w*a0.w;
        const float4 a1 = *(const float4*)(w1 + (k4 << 2));
        acc[1] += hv.x*a1.x + hv.y*a1.y + hv.z*a1.z + hv.w*a1.w;
        const float4 a2 = *(const float4*)(w2 + (k4 << 2));
        acc[2] += hv.x*a2.x + hv.y*a2.y + hv.z*a2.z + hv.w*a2.w;
        const float4 a3 = *(const float4*)(w3 + (k4 << 2));
        acc[3] += hv.x*a3.x + hv.y*a3.y + hv.z*a3.z + hv.w*a3.w;
    }
}

// one group (128 thr) accumulates acc[4] over K range [kbase, kbase+256)
// of hsrc[b][k] * W[n][k]; cp.async double-buffered, 8 chunks of 32.
__device__ __forceinline__ void accum_grp(float acc[4],
    const float* __restrict__ hsrc, const float* __restrict__ sW,
    int kbase, float* bufA, float* bufB, int barid, int b, int nq)
{
    acc[0] = acc[1] = acc[2] = acc[3] = 0.f;
    stage32(bufA, hsrc, kbase,      b, nq); CP_COMMIT();
    stage32(bufB, hsrc, kbase + 32, b, nq); CP_COMMIT();
    const float* wr = sW + (nq * 4) * WROW + kbase;
#pragma unroll 2
    for (int c = 0; c < 8; c++) {
        float* cur = (c & 1) ? bufB : bufA;
        CP_WAIT1();            // own chunk-c group complete
        barx(barid);           // everyone's chunk-c staging visible
        chunk_fma(acc, cur, wr + c * 32, b);
        barx(barid);           // all readers done -> cur reusable
        if (c + 2 < 8) stage32(cur, hsrc, kbase + (c + 2) * 32, b, nq);
        CP_COMMIT();           // commit every iter (empty ok) to keep count
    }
}

// ---------------------------------------------------------------------------
__global__ __launch_bounds__(TPB)
void rnn_recurrent_kernel(const float* __restrict__ Wh0,
                          const float* __restrict__ Wi1,
                          const float* __restrict__ Wh1,
                          const float* __restrict__ bi1,
                          const float* __restrict__ bh1,
                          float* __restrict__ out,
                          int write_final)
{
    extern __shared__ float smem[];
    float* sWh0 = smem;
    float* sWi1 = smem + NSL*WROW;
    float* sWh1 = smem + 2*NSL*WROW;
    float* stg  = smem + STG_OFF;
    float* red1 = smem + RED1_OFF;
    float* red2 = smem + RED2_OFF;

    const int tid   = threadIdx.x;
    const int nbase = blockIdx.x * NSL;
    const int grp   = tid >> 7;        // 0..3 : K-split group
    const int gt    = tid & 127;
    const int b     = gt >> 1;         // batch row 0..63
    const int nq    = gt & 1;          // column quad 0/1
    const int barid = grp + 1;
    const int kbase = grp * 256;
    float* bufA = stg + (grp * 2 + 0) * STG_BUF;
    float* bufB = stg + (grp * 2 + 1) * STG_BUF;

    // resident weight slices (8 rows each, padded stride WROW)
    {
        for (int i = tid; i < NSL * 256; i += TPB) {   // 256 float4 per row
            const int row = i >> 8, c4 = (i & 255) << 2;
            const size_t g = (size_t)(nbase + row) * HD + c4;
            *(float4*)(sWh0 + row * WROW + c4) = *(const float4*)(Wh0 + g);
            *(float4*)(sWi1 + row * WROW + c4) = *(const float4*)(Wi1 + g);
            *(float4*)(sWh1 + row * WROW + c4) = *(const float4*)(Wh1 + g);
        }
    }

    // per-thread epilogue constants: one output each (oo = tid)
    const int eb = tid >> 3;           // batch row
    const int en = tid & 7;            // column within slice
    const float bias = bi1[nbase + en] + bh1[nbase + en];
    __syncthreads();

    float acc[4];
    for (int t = 0; t < SEQ; t++) {
        const int rb = t & 1, wb = rb ^ 1;
        const float* h1p = g_h1[rb];
        float*       h1n = g_h1[wb];
        const float* h2p = g_h2[rb];
        float*       h2n = g_h2[wb];
        const int last = (t == SEQ - 1);

        // ---- W0: Wh0 x h1p (4-way K-split) -> h1(t) ----
        accum_grp(acc, h1p, sWh0, kbase, bufA, bufB, barid, b, nq);
        {
            float* r = red1 + grp * 512 + b * NSL + nq * 4;
            r[0]=acc[0]; r[1]=acc[1]; r[2]=acc[2]; r[3]=acc[3];
        }
        __syncthreads();
        {
            float v = red1[tid] + red1[512+tid] + red1[1024+tid] + red1[1536+tid]
                    + __ldg(&g_P[(size_t)t*BATCH*HD + (size_t)eb*HD + nbase + en]);
            v = tanhf(v);
            __stcg(&h1n[(size_t)eb*HD + nbase + en], v);
            if (write_final && last)
                out[OUT_MAIN + (size_t)eb*HD + nbase + en] = v;
        }
        grid_arrive(&g_c1);                         // publish h1(t)

        // h2p must be globally synced before W2 reads it (E2 of step t-1)
        grid_wait(&g_c2, (unsigned)t * NCTA);

        // ---- W2: Wh1 x h2p (independent of h1 sync -> hides E1 latency) ----
        accum_grp(acc, h2p, sWh1, kbase, bufA, bufB, barid, b, nq);
        {
            float* r = red2 + grp * 512 + b * NSL + nq * 4;
            r[0]=acc[0]; r[1]=acc[1]; r[2]=acc[2]; r[3]=acc[3];
        }

        // now h1(t) must be visible chip-wide
        grid_wait(&g_c1, (unsigned)(t + 1) * NCTA);

        // ---- W1: Wi1 x h1(t) ----
        accum_grp(acc, h1n, sWi1, kbase, bufA, bufB, barid, b, nq);
        {
            float* r = red1 + grp * 512 + b * NSL + nq * 4;
            r[0]=acc[0]; r[1]=acc[1]; r[2]=acc[2]; r[3]=acc[3];
        }
        __syncthreads();
        {
            float v = red1[tid] + red1[512+tid] + red1[1024+tid] + red1[1536+tid]
                    + red2[tid] + red2[512+tid] + red2[1024+tid] + red2[1536+tid]
                    + bias;
            v = tanhf(v);
            __stcg(&h2n[(size_t)eb*HD + nbase + en], v);
            __stcg(&out[(size_t)t*BATCH*HD + (size_t)eb*HD + nbase + en], v);
            if (write_final && last)
                out[OUT_MAIN + (size_t)BATCH*HD + (size_t)eb*HD + nbase + en] = v;
        }
        grid_arrive(&g_c2);                         // publish h2(t)
        // E2 waited at top of next iteration, hidden behind W0(t+1)
    }
}

// ---------------------------------------------------------------------------
extern "C" void kernel_launch(void* const* d_in, const int* in_sizes, int n_in,
                              void* d_out, int out_size) {
    const float* x   = (const float*)d_in[0];
    const float* Wi0 = (const float*)d_in[1];
    const float* bi0 = (const float*)d_in[2];
    const float* Wh0 = (const float*)d_in[3];
    const float* bh0 = (const float*)d_in[4];
    const float* Wi1 = (const float*)d_in[5];
    const float* bi1 = (const float*)d_in[6];
    const float* Wh1 = (const float*)d_in[7];
    const float* bh1 = (const float*)d_in[8];
    float* out = (float*)d_out;

    const int write_final =
        ((size_t)out_size >= OUT_MAIN + (size_t)2 * BATCH * HD) ? 1 : 0;

    cudaFuncSetAttribute(rnn_recurrent_kernel,
                         cudaFuncAttributeMaxDynamicSharedMemorySize, SMEM_BYTES);

    rnn_reset_kernel<<<(BATCH*HD + 255) / 256, 256>>>();
    rnn_precompute_kernel<<<dim3(HD/64, MTOT/64), 256>>>(x, Wi0, bi0, bh0);
    rnn_recurrent_kernel<<<NCTA, TPB, SMEM_BYTES>>>(Wh0, Wi1, Wh1, bi1, bh1,
                                                    out, write_final);
}

// round 5
// speedup vs baseline: 1.4574x; 1.0001x over previous
#include <cuda_runtime.h>
#include <math.h>
#include <stdint.h>

// ---------------------------------------------------------------------------
// Two-layer tanh RNN.  SEQ=512, BATCH=64, IN=HD=1024, fp32.
//   h1(t) = tanh(x(t)@Wi0^T + bi0 + h1(t-1)@Wh0^T + bh0)
//   h2(t) = tanh(h1(t)@Wi1^T + bi1 + h2(t-1)@Wh1^T + bh1)
// Output: outputs[512,64,1024] ++ h_final[2,64,1024].
//
//   1) reset      : zero barrier counters + initial hidden state
//   2) precompute : P = x@Wi0^T + bi0 + bh0 (unchanged, known-good)
//   3) recurrent  : persistent, 128 CTAs x 512 thr, weights in SMEM,
//                   cp.async h staging, split arrive/wait grid sync.
// ---------------------------------------------------------------------------

#define SEQ   512
#define BATCH 64
#define HD    1024
#define MTOT  (SEQ*BATCH)
#define OUT_MAIN ((size_t)SEQ*BATCH*HD)

#define NCTA 128
#define TPB  512
#define NSL  8                         // output columns per CTA

// smem layout (floats)
#define WROW   1028                    // 1024 + 4 pad: kills nq0/nq1 bank conflict
#define SW_FLOATS (3*NSL*WROW)         // 24672
#define STG_OFF   SW_FLOATS
#define STG_BUF   2048                 // one chunk: 64 rows x 32 k
#define RED1_OFF  (STG_OFF + 8*STG_BUF)    // 24672+16384 = 41056
#define RED2_OFF  (RED1_OFF + 2048)
#define SMEM_FLOATS (RED2_OFF + 2048)      // 45152
#define SMEM_BYTES  (SMEM_FLOATS*4)        // 180608

__device__ float g_P[33554432];        // 128 MB precomputed input term
__device__ float g_h1[2][BATCH*HD];
__device__ float g_h2[2][BATCH*HD];
__device__ unsigned g_c1, g_c2;

// ---------------------------------------------------------------------------
__global__ void rnn_reset_kernel() {
    unsigned idx = blockIdx.x * blockDim.x + threadIdx.x;
    if (idx == 0) { g_c1 = 0u; g_c2 = 0u; }
    if (idx < BATCH*HD) {
        g_h1[0][idx] = 0.f;
        g_h2[0][idx] = 0.f;
    }
}

// ---------------------------------------------------------------------------
// precompute (unchanged from passing R3 kernel)
// ---------------------------------------------------------------------------
__global__ __launch_bounds__(256)
void rnn_precompute_kernel(const float* __restrict__ X,
                           const float* __restrict__ Wi0,
                           const float* __restrict__ bi0,
                           const float* __restrict__ bh0)
{
    __shared__ float As[16][68];
    __shared__ float Bs[16][68];

    const int bm = blockIdx.y * 64;
    const int bn = blockIdx.x * 64;
    const int tid = threadIdx.x;
    const int ty = tid >> 4, tx = tid & 15;
    const int m0 = ty * 4, n0 = tx * 4;
    const int lm = tid >> 2;
    const int lk = (tid & 3) * 4;

    const float* Ap = X   + (size_t)(bm + lm) * HD + lk;
    const float* Bp = Wi0 + (size_t)(bn + lm) * HD + lk;

    float4 a = *(const float4*)Ap;
    float4 b = *(const float4*)Bp;

    float acc[4][4];
#pragma unroll
    for (int i = 0; i < 4; i++)
#pragma unroll
        for (int j = 0; j < 4; j++) acc[i][j] = 0.f;

    for (int k0 = 0; k0 < HD; k0 += 16) {
        __syncthreads();
        As[lk+0][lm] = a.x; As[lk+1][lm] = a.y; As[lk+2][lm] = a.z; As[lk+3][lm] = a.w;
        Bs[lk+0][lm] = b.x; Bs[lk+1][lm] = b.y; Bs[lk+2][lm] = b.z; Bs[lk+3][lm] = b.w;
        __syncthreads();
        if (k0 + 16 < HD) {
            a = *(const float4*)(Ap + k0 + 16);
            b = *(const float4*)(Bp + k0 + 16);
        }
#pragma unroll
        for (int k = 0; k < 16; k++) {
            const float4 av = *(const float4*)&As[k][m0];
            const float4 bv = *(const float4*)&Bs[k][n0];
            float am[4] = {av.x, av.y, av.z, av.w};
            float bb[4] = {bv.x, bv.y, bv.z, bv.w};
#pragma unroll
            for (int i = 0; i < 4; i++)
#pragma unroll
                for (int j = 0; j < 4; j++) acc[i][j] += am[i] * bb[j];
        }
    }

    const int gn = bn + n0;
    float b0[4];
#pragma unroll
    for (int j = 0; j < 4; j++) b0[j] = bi0[gn + j] + bh0[gn + j];
#pragma unroll
    for (int i = 0; i < 4; i++) {
        float4 r;
        r.x = acc[i][0] + b0[0];
        r.y = acc[i][1] + b0[1];
        r.z = acc[i][2] + b0[2];
        r.w = acc[i][3] + b0[3];
        *(float4*)&g_P[(size_t)(bm + m0 + i) * HD + gn] = r;
    }
}

// ---------------------------------------------------------------------------
// recurrent kernel helpers
// ---------------------------------------------------------------------------
__device__ __forceinline__ void barx(int id) {
    asm volatile("bar.sync %0, %1;" :: "r"(id), "r"(128) : "memory");
}

// split grid barrier: arrive once per CTA, wait for target arrivals
__device__ __forceinline__ void grid_arrive(unsigned* c) {
    __threadfence();
    __syncthreads();
    if (threadIdx.x == 0) atomicAdd(c, 1u);
}
__device__ __forceinline__ void grid_wait(unsigned* c, unsigned target) {
    if (threadIdx.x == 0) {
        while (*((volatile unsigned*)c) < target) __nanosleep(32);
        __threadfence();
    }
    __syncthreads();
}

__device__ __forceinline__ unsigned sptr(const void* p) {
    return (unsigned)__cvta_generic_to_shared(p);
}
#define CP_COMMIT() asm volatile("cp.async.commit_group;" ::: "memory")
#define CP_WAIT1()  asm volatile("cp.async.wait_group 1;" ::: "memory")

// stage one 64x32 chunk of h (rows 0..63, k in [k0,k0+32)) into swizzled buf.
// thread (row=b, j): 4x cp.async.cg 16B. dst word = row*32 + ((k4+row)&7)*4.
__device__ __forceinline__ void stage32(float* buf, const float* src,
                                        int k0, int row, int j) {
    const float* s = src + (size_t)row * HD + k0 + j * 16;
    unsigned d = sptr(buf + row * 32);
#pragma unroll
    for (int i = 0; i < 4; i++) {
        const int k4 = j * 4 + i;
        unsigned dd = d + (((k4 + row) & 7) << 4);
        asm volatile("cp.async.cg.shared.global [%0], [%1], 16;"
                     :: "r"(dd), "l"(s + i * 4) : "memory");
    }
}

// 8 k4-iterations over one staged chunk; weights from SMEM (broadcast).
__device__ __forceinline__ void chunk_fma(float acc[4], const float* buf,
                                          const float* w0, int b) {
    const float* hrow = buf + b * 32;
    const float* w1 = w0 + WROW;
    const float* w2 = w0 + 2 * WROW;
    const float* w3 = w0 + 3 * WROW;
#pragma unroll
    for (int k4 = 0; k4 < 8; k4++) {
        const float4 hv = *(const float4*)(hrow + (((k4 + b) & 7) << 2));
        const float4 a0 = *(const float4*)(w0 + (k4 << 2));
        acc[0] += hv.x*a0.x + hv.y*a0.y + hv.z*a0.z + hv.w*a0.w;
        const float4 a1 = *(const float4*)(w1 + (k4 << 2));
        acc[1] += hv.x*a1.x + hv.y*a1.y + hv.z*a1.z + hv.w*a1.w;
        const float4 a2 = *(const float4*)(w2 + (k4 << 2));
        acc[2] += hv.x*a2.x + hv.y*a2.y + hv.z*a2.z + hv.w*a2.w;
        const float4 a3 = *(const float4*)(w3 + (k4 << 2));
        acc[3] += hv.x*a3.x + hv.y*a3.y + hv.z*a3.z + hv.w*a3.w;
    }
}

// one group (128 thr) accumulates acc[4] over K range [kbase, kbase+256)
// of hsrc[b][k] * W[n][k]; cp.async double-buffered, 8 chunks of 32.
__device__ __forceinline__ void accum_grp(float acc[4],
    const float* __restrict__ hsrc, const float* __restrict__ sW,
    int kbase, float* bufA, float* bufB, int barid, int b, int nq)
{
    acc[0] = acc[1] = acc[2] = acc[3] = 0.f;
    stage32(bufA, hsrc, kbase,      b, nq); CP_COMMIT();
    stage32(bufB, hsrc, kbase + 32, b, nq); CP_COMMIT();
    const float* wr = sW + (nq * 4) * WROW + kbase;
#pragma unroll 2
    for (int c = 0; c < 8; c++) {
        float* cur = (c & 1) ? bufB : bufA;
        CP_WAIT1();            // own chunk-c group complete
        barx(barid);           // everyone's chunk-c staging visible
        chunk_fma(acc, cur, wr + c * 32, b);
        barx(barid);           // all readers done -> cur reusable
        if (c + 2 < 8) stage32(cur, hsrc, kbase + (c + 2) * 32, b, nq);
        CP_COMMIT();           // commit every iter (empty ok) to keep count
    }
}

// ---------------------------------------------------------------------------
__global__ __launch_bounds__(TPB)
void rnn_recurrent_kernel(const float* __restrict__ Wh0,
                          const float* __restrict__ Wi1,
                          const float* __restrict__ Wh1,
                          const float* __restrict__ bi1,
                          const float* __restrict__ bh1,
                          float* __restrict__ out,
                          int write_final)
{
    extern __shared__ float smem[];
    float* sWh0 = smem;
    float* sWi1 = smem + NSL*WROW;
    float* sWh1 = smem + 2*NSL*WROW;
    float* stg  = smem + STG_OFF;
    float* red1 = smem + RED1_OFF;
    float* red2 = smem + RED2_OFF;

    const int tid   = threadIdx.x;
    const int nbase = blockIdx.x * NSL;
    const int grp   = tid >> 7;        // 0..3 : K-split group
    const int gt    = tid & 127;
    const int b     = gt >> 1;         // batch row 0..63
    const int nq    = gt & 1;          // column quad 0/1
    const int barid = grp + 1;
    const int kbase = grp * 256;
    float* bufA = stg + (grp * 2 + 0) * STG_BUF;
    float* bufB = stg + (grp * 2 + 1) * STG_BUF;

    // resident weight slices (8 rows each, padded stride WROW)
    {
        for (int i = tid; i < NSL * 256; i += TPB) {   // 256 float4 per row
            const int row = i >> 8, c4 = (i & 255) << 2;
            const size_t g = (size_t)(nbase + row) * HD + c4;
            *(float4*)(sWh0 + row * WROW + c4) = *(const float4*)(Wh0 + g);
            *(float4*)(sWi1 + row * WROW + c4) = *(const float4*)(Wi1 + g);
            *(float4*)(sWh1 + row * WROW + c4) = *(const float4*)(Wh1 + g);
        }
    }

    // per-thread epilogue constants: one output each (oo = tid)
    const int eb = tid >> 3;           // batch row
    const int en = tid & 7;            // column within slice
    const float bias = bi1[nbase + en] + bh1[nbase + en];
    __syncthreads();

    float acc[4];
    for (int t = 0; t < SEQ; t++) {
        const int rb = t & 1, wb = rb ^ 1;
        const float* h1p = g_h1[rb];
        float*       h1n = g_h1[wb];
        const float* h2p = g_h2[rb];
        float*       h2n = g_h2[wb];
        const int last = (t == SEQ - 1);

        // ---- W0: Wh0 x h1p (4-way K-split) -> h1(t) ----
        accum_grp(acc, h1p, sWh0, kbase, bufA, bufB, barid, b, nq);
        {
            float* r = red1 + grp * 512 + b * NSL + nq * 4;
            r[0]=acc[0]; r[1]=acc[1]; r[2]=acc[2]; r[3]=acc[3];
        }
        __syncthreads();
        {
            float v = red1[tid] + red1[512+tid] + red1[1024+tid] + red1[1536+tid]
                    + __ldg(&g_P[(size_t)t*BATCH*HD + (size_t)eb*HD + nbase + en]);
            v = tanhf(v);
            __stcg(&h1n[(size_t)eb*HD + nbase + en], v);
            if (write_final && last)
                out[OUT_MAIN + (size_t)eb*HD + nbase + en] = v;
        }
        grid_arrive(&g_c1);                         // publish h1(t)

        // h2p must be globally synced before W2 reads it (E2 of step t-1)
        grid_wait(&g_c2, (unsigned)t * NCTA);

        // ---- W2: Wh1 x h2p (independent of h1 sync -> hides E1 latency) ----
        accum_grp(acc, h2p, sWh1, kbase, bufA, bufB, barid, b, nq);
        {
            float* r = red2 + grp * 512 + b * NSL + nq * 4;
            r[0]=acc[0]; r[1]=acc[1]; r[2]=acc[2]; r[3]=acc[3];
        }

        // now h1(t) must be visible chip-wide
        grid_wait(&g_c1, (unsigned)(t + 1) * NCTA);

        // ---- W1: Wi1 x h1(t) ----
        accum_grp(acc, h1n, sWi1, kbase, bufA, bufB, barid, b, nq);
        {
            float* r = red1 + grp * 512 + b * NSL + nq * 4;
            r[0]=acc[0]; r[1]=acc[1]; r[2]=acc[2]; r[3]=acc[3];
        }
        __syncthreads();
        {
            float v = red1[tid] + red1[512+tid] + red1[1024+tid] + red1[1536+tid]
                    + red2[tid] + red2[512+tid] + red2[1024+tid] + red2[1536+tid]
                    + bias;
            v = tanhf(v);
            __stcg(&h2n[(size_t)eb*HD + nbase + en], v);
            __stcg(&out[(size_t)t*BATCH*HD + (size_t)eb*HD + nbase + en], v);
            if (write_final && last)
                out[OUT_MAIN + (size_t)BATCH*HD + (size_t)eb*HD + nbase + en] = v;
        }
        grid_arrive(&g_c2);                         // publish h2(t)
        // E2 waited at top of next iteration, hidden behind W0(t+1)
    }
}

// ---------------------------------------------------------------------------
extern "C" void kernel_launch(void* const* d_in, const int* in_sizes, int n_in,
                              void* d_out, int out_size) {
    const float* x   = (const float*)d_in[0];
    const float* Wi0 = (const float*)d_in[1];
    const float* bi0 = (const float*)d_in[2];
    const float* Wh0 = (const float*)d_in[3];
    const float* bh0 = (const float*)d_in[4];
    const float* Wi1 = (const float*)d_in[5];
    const float* bi1 = (const float*)d_in[6];
    const float* Wh1 = (const float*)d_in[7];
    const float* bh1 = (const float*)d_in[8];
    float* out = (float*)d_out;

    const int write_final =
        ((size_t)out_size >= OUT_MAIN + (size_t)2 * BATCH * HD) ? 1 : 0;

    cudaFuncSetAttribute(rnn_recurrent_kernel,
                         cudaFuncAttributeMaxDynamicSharedMemorySize, SMEM_BYTES);

    rnn_reset_kernel<<<(BATCH*HD + 255) / 256, 256>>>();
    rnn_precompute_kernel<<<dim3(HD/64, MTOT/64), 256>>>(x, Wi0, bi0, bh0);
    rnn_recurrent_kernel<<<NCTA, TPB, SMEM_BYTES>>>(Wh0, Wi1, Wh1, bi1, bh1,
                                                    out, write_final);
}

// round 6
// speedup vs baseline: 1.8707x; 1.2836x over previous
#include <cuda_runtime.h>
#include <cuda_bf16.h>
#include <math.h>
#include <stdint.h>

#define SEQ   512
#define BATCH 64
#define HD    1024
#define MTOT  (SEQ*BATCH)
#define OUT_MAIN ((size_t)SEQ*BATCH*HD)
#define NCTA 64
#define TPB  256

typedef unsigned long long u64;

#define GH_ENT 16384                    // packed h: [mt4][kb64][g8][c8]
#define GW_ENT 262144                   // packed W: [nfg128][kb64][g8][tg4]
#define SB_ENT 4096                     // per-CTA W slice entries (32KB)
#define SMEM_BYTES (6*SB_ENT*8 + 32768) // 229376

__device__ float g_P[33554432];
__device__ u64 g_h1hi[2][GH_ENT], g_h1lo[2][GH_ENT];
__device__ u64 g_h2hi[2][GH_ENT], g_h2lo[2][GH_ENT];
__device__ u64 g_Wp[3][2][GW_ENT];      // [Wh0,Wi1,Wh1][hi,lo]
__device__ unsigned g_c1, g_c2;

__device__ __forceinline__ uint2 ldcg2(const u64* p) {
    uint2 v;
    asm volatile("ld.global.cg.v2.u32 {%0,%1},[%2];" : "=r"(v.x), "=r"(v.y) : "l"(p));
    return v;
}
__device__ __forceinline__ void stcg64(u64* p, u64 v) {
    asm volatile("st.global.cg.u64 [%0],%1;" :: "l"(p), "l"(v));
}
__device__ __forceinline__ void mma16816(float d[4], uint2 a01, uint2 a23, uint2 b) {
    asm volatile(
        "mma.sync.aligned.m16n8k16.row.col.f32.bf16.bf16.f32 "
        "{%0,%1,%2,%3},{%4,%5,%6,%7},{%8,%9},{%0,%1,%2,%3};"
        : "+f"(d[0]), "+f"(d[1]), "+f"(d[2]), "+f"(d[3])
        : "r"(a01.x), "r"(a01.y), "r"(a23.x), "r"(a23.y), "r"(b.x), "r"(b.y));
}
__device__ __forceinline__ unsigned short bfu(float x) {
    return __bfloat16_as_ushort(__float2bfloat16(x));
}
__device__ __forceinline__ void pack_hilo(float v0, float v1, float v2, float v3,
                                          u64& hi, u64& lo) {
    unsigned short h0 = bfu(v0), h1 = bfu(v1), h2 = bfu(v2), h3 = bfu(v3);
    unsigned short l0 = bfu(v0 - __bfloat162float(__ushort_as_bfloat16(h0)));
    unsigned short l1 = bfu(v1 - __bfloat162float(__ushort_as_bfloat16(h1)));
    unsigned short l2 = bfu(v2 - __bfloat162float(__ushort_as_bfloat16(h2)));
    unsigned short l3 = bfu(v3 - __bfloat162float(__ushort_as_bfloat16(h3)));
    hi = (u64)h0 | ((u64)h1 << 16) | ((u64)h2 << 32) | ((u64)h3 << 48);
    lo = (u64)l0 | ((u64)l1 << 16) | ((u64)l2 << 32) | ((u64)l3 << 48);
}

// ---------------------------------------------------------------------------
__global__ void rnn_reset_kernel() {
    unsigned idx = blockIdx.x * blockDim.x + threadIdx.x;
    if (idx == 0) { g_c1 = 0u; g_c2 = 0u; }
    if (idx < GH_ENT) {
        g_h1hi[0][idx] = 0ull; g_h1lo[0][idx] = 0ull;
        g_h2hi[0][idx] = 0ull; g_h2lo[0][idx] = 0ull;
    }
}

// pack W[n][k] into B-fragment entries: (nfg,kb,g,tg) = W[nfg*8+g][kb*16+2tg..]
__global__ __launch_bounds__(256)
void rnn_prepw_kernel(const float* __restrict__ Wh0,
                      const float* __restrict__ Wi1,
                      const float* __restrict__ Wh1)
{
    unsigned idx = blockIdx.x * blockDim.x + threadIdx.x;
    if (idx >= 3u * GW_ENT) return;
    const int m = idx / GW_ENT;
    const unsigned e = idx % GW_ENT;
    const int nfg = e >> 11;
    const int kb  = (e >> 5) & 63;
    const int gg  = (e >> 2) & 7;
    const int tg  = e & 3;
    const float* W = (m == 0) ? Wh0 : (m == 1) ? Wi1 : Wh1;
    const float* p = W + (size_t)(nfg * 8 + gg) * HD + kb * 16 + tg * 2;
    u64 hi, lo;
    pack_hilo(p[0], p[1], p[8], p[9], hi, lo);
    g_Wp[m][0][e] = hi;
    g_Wp[m][1][e] = lo;
}

// ---------------------------------------------------------------------------
// precompute (proven fp32): P = x@Wi0^T + bi0 + bh0
// ---------------------------------------------------------------------------
__global__ __launch_bounds__(256)
void rnn_precompute_kernel(const float* __restrict__ X,
                           const float* __restrict__ Wi0,
                           const float* __restrict__ bi0,
                           const float* __restrict__ bh0)
{
    __shared__ float As[16][68];
    __shared__ float Bs[16][68];
    const int bm = blockIdx.y * 64, bn = blockIdx.x * 64;
    const int tid = threadIdx.x;
    const int m0 = (tid >> 4) * 4, n0 = (tid & 15) * 4;
    const int lm = tid >> 2, lk = (tid & 3) * 4;
    const float* Ap = X   + (size_t)(bm + lm) * HD + lk;
    const float* Bp = Wi0 + (size_t)(bn + lm) * HD + lk;
    float4 a = *(const float4*)Ap;
    float4 b = *(const float4*)Bp;
    float acc[4][4];
#pragma unroll
    for (int i = 0; i < 4; i++)
#pragma unroll
        for (int j = 0; j < 4; j++) acc[i][j] = 0.f;
    for (int k0 = 0; k0 < HD; k0 += 16) {
        __syncthreads();
        As[lk+0][lm] = a.x; As[lk+1][lm] = a.y; As[lk+2][lm] = a.z; As[lk+3][lm] = a.w;
        Bs[lk+0][lm] = b.x; Bs[lk+1][lm] = b.y; Bs[lk+2][lm] = b.z; Bs[lk+3][lm] = b.w;
        __syncthreads();
        if (k0 + 16 < HD) {
            a = *(const float4*)(Ap + k0 + 16);
            b = *(const float4*)(Bp + k0 + 16);
        }
#pragma unroll
        for (int k = 0; k < 16; k++) {
            const float4 av = *(const float4*)&As[k][m0];
            const float4 bv = *(const float4*)&Bs[k][n0];
            float am[4] = {av.x, av.y, av.z, av.w};
            float bb[4] = {bv.x, bv.y, bv.z, bv.w};
#pragma unroll
            for (int i = 0; i < 4; i++)
#pragma unroll
                for (int j = 0; j < 4; j++) acc[i][j] += am[i] * bb[j];
        }
    }
    const int gn = bn + n0;
    float b0[4];
#pragma unroll
    for (int j = 0; j < 4; j++) b0[j] = bi0[gn + j] + bh0[gn + j];
#pragma unroll
    for (int i = 0; i < 4; i++) {
        float4 r = make_float4(acc[i][0]+b0[0], acc[i][1]+b0[1],
                               acc[i][2]+b0[2], acc[i][3]+b0[3]);
        *(float4*)&g_P[(size_t)(bm + m0 + i) * HD + gn] = r;
    }
}

// ---------------------------------------------------------------------------
__device__ __forceinline__ void grid_arrive(unsigned* c) {
    __threadfence();
    __syncthreads();
    if (threadIdx.x == 0) atomicAdd(c, 1u);
}
__device__ __forceinline__ void grid_wait(unsigned* c, unsigned target) {
    if (threadIdx.x == 0) {
        while (*((volatile unsigned*)c) < target) __nanosleep(32);
        __threadfence();
    }
    __syncthreads();
}

// warp GEMM slice: D[u=mt*2+nf][4] += A(k-slice kb0..kb0+8) x B, 3-term hi/lo
__device__ __forceinline__ void gemm_acc(float (&D)[8][4],
    const u64* __restrict__ ghHi, const u64* __restrict__ ghLo,
    const u64* __restrict__ sBhi, int kb0, int gg, int tg)
{
    uint2 cAh01[4], cAh23[4], cAl01[4], cAl23[4];
#pragma unroll
    for (int mt = 0; mt < 4; mt++) {
        const size_t base = ((size_t)(mt * 64 + kb0) << 6) + (gg << 3) + tg;
        cAh01[mt] = ldcg2(ghHi + base);  cAh23[mt] = ldcg2(ghHi + base + 4);
        cAl01[mt] = ldcg2(ghLo + base);  cAl23[mt] = ldcg2(ghLo + base + 4);
    }
#pragma unroll
    for (int j = 0; j < 8; j++) {
        const int kb = kb0 + j;
        const int bi = (kb << 5) + (gg << 2) + tg;
        const uint2 Bh0 = *(const uint2*)(sBhi + bi);
        const uint2 Bh1 = *(const uint2*)(sBhi + 2048 + bi);
        const uint2 Bl0 = *(const uint2*)(sBhi + SB_ENT + bi);
        const uint2 Bl1 = *(const uint2*)(sBhi + SB_ENT + 2048 + bi);
        uint2 nAh01[4], nAh23[4], nAl01[4], nAl23[4];
        if (j < 7) {
#pragma unroll
            for (int mt = 0; mt < 4; mt++) {
                const size_t base = ((size_t)(mt * 64 + kb + 1) << 6) + (gg << 3) + tg;
                nAh01[mt] = ldcg2(ghHi + base);  nAh23[mt] = ldcg2(ghHi + base + 4);
                nAl01[mt] = ldcg2(ghLo + base);  nAl23[mt] = ldcg2(ghLo + base + 4);
            }
        }
#pragma unroll
        for (int mt = 0; mt < 4; mt++) {
            mma16816(D[mt*2+0], cAh01[mt], cAh23[mt], Bh0);
            mma16816(D[mt*2+0], cAh01[mt], cAh23[mt], Bl0);
            mma16816(D[mt*2+0], cAl01[mt], cAl23[mt], Bh0);
            mma16816(D[mt*2+1], cAh01[mt], cAh23[mt], Bh1);
            mma16816(D[mt*2+1], cAh01[mt], cAh23[mt], Bl1);
            mma16816(D[mt*2+1], cAl01[mt], cAl23[mt], Bh1);
        }
        if (j < 7) {
#pragma unroll
            for (int mt = 0; mt < 4; mt++) {
                cAh01[mt] = nAh01[mt]; cAh23[mt] = nAh23[mt];
                cAl01[mt] = nAl01[mt]; cAl23[mt] = nAl23[mt];
            }
        }
    }
}

// cross-warp K reduction: warp wid ends with summed unit u=wid in r[4]
__device__ __forceinline__ void kreduce(const float (&D)[8][4], float* sred,
                                        int wid, int lane, float r[4])
{
    const int sw = lane & 7;
#pragma unroll
    for (int u = 0; u < 8; u++) {
        float4* p = (float4*)&sred[((((u * 32 + lane) << 3) + (wid ^ sw)) << 2)];
        *p = make_float4(D[u][0], D[u][1], D[u][2], D[u][3]);
    }
    __syncthreads();
    r[0] = r[1] = r[2] = r[3] = 0.f;
#pragma unroll
    for (int w = 0; w < 8; w++) {
        float4 v = *(const float4*)&sred[((((wid * 32 + lane) << 3) + (w ^ sw)) << 2)];
        r[0] += v.x; r[1] += v.y; r[2] += v.z; r[3] += v.w;
    }
    __syncthreads();
}

// ---------------------------------------------------------------------------
__global__ __launch_bounds__(TPB)
void rnn_recurrent_kernel(const float* __restrict__ bi1,
                          const float* __restrict__ bh1,
                          float* __restrict__ out,
                          int write_final)
{
    extern __shared__ u64 smem_u64[];
    u64*   sB   = smem_u64;                        // 6 x SB_ENT
    float* sred = (float*)(smem_u64 + 6*SB_ENT);   // 8192 f32

    const int tid  = threadIdx.x;
    const int wid  = tid >> 5;
    const int lane = tid & 31;
    const int gg   = lane >> 2;
    const int tg   = lane & 3;
    const int cta  = blockIdx.x;
    const int kb0  = wid * 8;

    // load 6 x 32KB weight slices (contiguous per matrix/prec)
#pragma unroll
    for (int mp = 0; mp < 6; mp++) {
        const u64* src = g_Wp[mp >> 1][mp & 1] + (size_t)cta * SB_ENT;
        u64* dst = sB + mp * SB_ENT;
        for (int i = tid * 2; i < SB_ENT; i += TPB * 2)
            *(uint4*)(dst + i) = *(const uint4*)(src + i);
    }

    // epilogue coords: unit u = wid
    const int mt = wid >> 1, nf = wid & 1;
    const int m0 = mt * 16 + gg;                   // rows m0, m0+8
    const int n0 = cta * 16 + nf * 8 + tg * 2;     // cols n0, n0+1
    const unsigned ei = (unsigned)((mt * 64 + cta) << 6) + (gg << 3) + (nf * 4 + tg);
    const float bias0 = bi1[n0] + bh1[n0];
    const float bias1 = bi1[n0+1] + bh1[n0+1];
    __syncthreads();

    float D[8][4], r[4];
    for (int t = 0; t < SEQ; t++) {
        const int rb = t & 1, wb = rb ^ 1;
        const int last = (t == SEQ - 1);

#pragma unroll
        for (int u = 0; u < 8; u++)
            D[u][0] = D[u][1] = D[u][2] = D[u][3] = 0.f;

        // ---- layer 1: Wh0 x h1p ----
        gemm_acc(D, g_h1hi[rb], g_h1lo[rb], sB, kb0, gg, tg);
        kreduce(D, sred, wid, lane, r);
        {
            const float* Pt = g_P + (size_t)t * BATCH * HD;
            const float2 p0 = __ldg((const float2*)(Pt + (size_t)m0 * HD + n0));
            const float2 p1 = __ldg((const float2*)(Pt + (size_t)(m0+8) * HD + n0));
            float v0 = tanhf(r[0] + p0.x), v1 = tanhf(r[1] + p0.y);
            float v2 = tanhf(r[2] + p1.x), v3 = tanhf(r[3] + p1.y);
            u64 hi, lo; pack_hilo(v0, v1, v2, v3, hi, lo);
            stcg64(&g_h1hi[wb][ei], hi);
            stcg64(&g_h1lo[wb][ei], lo);
            if (write_final && last) {
                *(float2*)&out[OUT_MAIN + (size_t)m0*HD + n0]     = make_float2(v0, v1);
                *(float2*)&out[OUT_MAIN + (size_t)(m0+8)*HD + n0] = make_float2(v2, v3);
            }
        }
        grid_arrive(&g_c1);                        // publish h1(t)

        grid_wait(&g_c2, (unsigned)t * NCTA);      // h2p globally visible

#pragma unroll
        for (int u = 0; u < 8; u++)
            D[u][0] = D[u][1] = D[u][2] = D[u][3] = 0.f;

        // ---- layer 2a: Wh1 x h2p (hides c1 wait) ----
        gemm_acc(D, g_h2hi[rb], g_h2lo[rb], sB + 4*SB_ENT, kb0, gg, tg);

        grid_wait(&g_c1, (unsigned)(t + 1) * NCTA); // h1(t) globally visible

        // ---- layer 2b: Wi1 x h1(t), same accumulator ----
        gemm_acc(D, g_h1hi[wb], g_h1lo[wb], sB + 2*SB_ENT, kb0, gg, tg);
        kreduce(D, sred, wid, lane, r);
        {
            float v0 = tanhf(r[0] + bias0), v1 = tanhf(r[1] + bias1);
            float v2 = tanhf(r[2] + bias0), v3 = tanhf(r[3] + bias1);
            u64 hi, lo; pack_hilo(v0, v1, v2, v3, hi, lo);
            stcg64(&g_h2hi[wb][ei], hi);
            stcg64(&g_h2lo[wb][ei], lo);
            float* ot = out + (size_t)t * BATCH * HD;
            *(float2*)&ot[(size_t)m0*HD + n0]     = make_float2(v0, v1);
            *(float2*)&ot[(size_t)(m0+8)*HD + n0] = make_float2(v2, v3);
            if (write_final && last) {
                float* hf = out + OUT_MAIN + (size_t)BATCH*HD;
                *(float2*)&hf[(size_t)m0*HD + n0]     = make_float2(v0, v1);
                *(float2*)&hf[(size_t)(m0+8)*HD + n0] = make_float2(v2, v3);
            }
        }
        grid_arrive(&g_c2);                        // publish h2(t)
    }
}

// ---------------------------------------------------------------------------
extern "C" void kernel_launch(void* const* d_in, const int* in_sizes, int n_in,
                              void* d_out, int out_size) {
    const float* x   = (const float*)d_in[0];
    const float* Wi0 = (const float*)d_in[1];
    const float* bi0 = (const float*)d_in[2];
    const float* Wh0 = (const float*)d_in[3];
    const float* bh0 = (const float*)d_in[4];
    const float* Wi1 = (const float*)d_in[5];
    const float* bi1 = (const float*)d_in[6];
    const float* Wh1 = (const float*)d_in[7];
    const float* bh1 = (const float*)d_in[8];
    float* out = (float*)d_out;

    const int write_final =
        ((size_t)out_size >= OUT_MAIN + (size_t)2 * BATCH * HD) ? 1 : 0;

    cudaFuncSetAttribute(rnn_recurrent_kernel,
                         cudaFuncAttributeMaxDynamicSharedMemorySize, SMEM_BYTES);

    rnn_reset_kernel<<<256, 256>>>();
    rnn_prepw_kernel<<<(3*GW_ENT + 255)/256, 256>>>(Wh0, Wi1, Wh1);
    rnn_precompute_kernel<<<dim3(HD/64, MTOT/64), 256>>>(x, Wi0, bi0, bh0);
    rnn_recurrent_kernel<<<NCTA, TPB, SMEM_BYTES>>>(bi1, bh1, out, write_final);
}

// round 7
// speedup vs baseline: 2.5667x; 1.3721x over previous
#include <cuda_runtime.h>
#include <cuda_bf16.h>
#include <math.h>
#include <stdint.h>

#define SEQ   512
#define BATCH 64
#define HD    1024
#define MTOT  (SEQ*BATCH)
#define OUT_MAIN ((size_t)SEQ*BATCH*HD)
#define NCTA 64
#define TPB  512

typedef unsigned long long u64;

#define GH_ENT 16384                    // packed h: [mt4][kb64][g8][c8]
#define GW_ENT 262144                   // packed W: [nfg128][kb64][g8][tg4]
#define SB_ENT 4096                     // per-CTA W slice entries (32KB)
#define SMEM_BYTES (6*SB_ENT*8 + 32768) // 229376

__device__ float g_P[33554432];
__device__ u64 g_h1hi[2][GH_ENT], g_h1lo[2][GH_ENT];
__device__ u64 g_h2hi[2][GH_ENT], g_h2lo[2][GH_ENT];
__device__ u64 g_Wp[3][2][GW_ENT];      // [Wh0,Wi1,Wh1][hi,lo]
__device__ unsigned g_c1, g_c2;

__device__ __forceinline__ uint2 ldcg2(const u64* p) {
    uint2 v;
    asm volatile("ld.global.cg.v2.u32 {%0,%1},[%2];" : "=r"(v.x), "=r"(v.y) : "l"(p));
    return v;
}
__device__ __forceinline__ void stcg64(u64* p, u64 v) {
    asm volatile("st.global.cg.u64 [%0],%1;" :: "l"(p), "l"(v));
}
__device__ __forceinline__ void mma16816(float d[4], uint2 a01, uint2 a23, uint2 b) {
    asm volatile(
        "mma.sync.aligned.m16n8k16.row.col.f32.bf16.bf16.f32 "
        "{%0,%1,%2,%3},{%4,%5,%6,%7},{%8,%9},{%0,%1,%2,%3};"
        : "+f"(d[0]), "+f"(d[1]), "+f"(d[2]), "+f"(d[3])
        : "r"(a01.x), "r"(a01.y), "r"(a23.x), "r"(a23.y), "r"(b.x), "r"(b.y));
}
__device__ __forceinline__ unsigned short bfu(float x) {
    return __bfloat16_as_ushort(__float2bfloat16(x));
}
__device__ __forceinline__ void pack_hilo(float v0, float v1, float v2, float v3,
                                          u64& hi, u64& lo) {
    unsigned short h0 = bfu(v0), h1 = bfu(v1), h2 = bfu(v2), h3 = bfu(v3);
    unsigned short l0 = bfu(v0 - __bfloat162float(__ushort_as_bfloat16(h0)));
    unsigned short l1 = bfu(v1 - __bfloat162float(__ushort_as_bfloat16(h1)));
    unsigned short l2 = bfu(v2 - __bfloat162float(__ushort_as_bfloat16(h2)));
    unsigned short l3 = bfu(v3 - __bfloat162float(__ushort_as_bfloat16(h3)));
    hi = (u64)h0 | ((u64)h1 << 16) | ((u64)h2 << 32) | ((u64)h3 << 48);
    lo = (u64)l0 | ((u64)l1 << 16) | ((u64)l2 << 32) | ((u64)l3 << 48);
}

// ---------------------------------------------------------------------------
__global__ void rnn_reset_kernel() {
    unsigned idx = blockIdx.x * blockDim.x + threadIdx.x;
    if (idx == 0) { g_c1 = 0u; g_c2 = 0u; }
    if (idx < GH_ENT) {
        g_h1hi[0][idx] = 0ull; g_h1lo[0][idx] = 0ull;
        g_h2hi[0][idx] = 0ull; g_h2lo[0][idx] = 0ull;
    }
}

__global__ __launch_bounds__(256)
void rnn_prepw_kernel(const float* __restrict__ Wh0,
                      const float* __restrict__ Wi1,
                      const float* __restrict__ Wh1)
{
    unsigned idx = blockIdx.x * blockDim.x + threadIdx.x;
    if (idx >= 3u * GW_ENT) return;
    const int m = idx / GW_ENT;
    const unsigned e = idx % GW_ENT;
    const int nfg = e >> 11, kb = (e >> 5) & 63, gg = (e >> 2) & 7, tg = e & 3;
    const float* W = (m == 0) ? Wh0 : (m == 1) ? Wi1 : Wh1;
    const float* p = W + (size_t)(nfg * 8 + gg) * HD + kb * 16 + tg * 2;
    u64 hi, lo;
    pack_hilo(p[0], p[1], p[8], p[9], hi, lo);
    g_Wp[m][0][e] = hi;
    g_Wp[m][1][e] = lo;
}

// ---------------------------------------------------------------------------
// precompute (proven fp32): P = x@Wi0^T + bi0 + bh0
// ---------------------------------------------------------------------------
__global__ __launch_bounds__(256)
void rnn_precompute_kernel(const float* __restrict__ X,
                           const float* __restrict__ Wi0,
                           const float* __restrict__ bi0,
                           const float* __restrict__ bh0)
{
    __shared__ float As[16][68];
    __shared__ float Bs[16][68];
    const int bm = blockIdx.y * 64, bn = blockIdx.x * 64;
    const int tid = threadIdx.x;
    const int m0 = (tid >> 4) * 4, n0 = (tid & 15) * 4;
    const int lm = tid >> 2, lk = (tid & 3) * 4;
    const float* Ap = X   + (size_t)(bm + lm) * HD + lk;
    const float* Bp = Wi0 + (size_t)(bn + lm) * HD + lk;
    float4 a = *(const float4*)Ap;
    float4 b = *(const float4*)Bp;
    float acc[4][4];
#pragma unroll
    for (int i = 0; i < 4; i++)
#pragma unroll
        for (int j = 0; j < 4; j++) acc[i][j] = 0.f;
    for (int k0 = 0; k0 < HD; k0 += 16) {
        __syncthreads();
        As[lk+0][lm] = a.x; As[lk+1][lm] = a.y; As[lk+2][lm] = a.z; As[lk+3][lm] = a.w;
        Bs[lk+0][lm] = b.x; Bs[lk+1][lm] = b.y; Bs[lk+2][lm] = b.z; Bs[lk+3][lm] = b.w;
        __syncthreads();
        if (k0 + 16 < HD) {
            a = *(const float4*)(Ap + k0 + 16);
            b = *(const float4*)(Bp + k0 + 16);
        }
#pragma unroll
        for (int k = 0; k < 16; k++) {
            const float4 av = *(const float4*)&As[k][m0];
            const float4 bv = *(const float4*)&Bs[k][n0];
            float am[4] = {av.x, av.y, av.z, av.w};
            float bb[4] = {bv.x, bv.y, bv.z, bv.w};
#pragma unroll
            for (int i = 0; i < 4; i++)
#pragma unroll
                for (int j = 0; j < 4; j++) acc[i][j] += am[i] * bb[j];
        }
    }
    const int gn = bn + n0;
    float b0[4];
#pragma unroll
    for (int j = 0; j < 4; j++) b0[j] = bi0[gn + j] + bh0[gn + j];
#pragma unroll
    for (int i = 0; i < 4; i++) {
        float4 r = make_float4(acc[i][0]+b0[0], acc[i][1]+b0[1],
                               acc[i][2]+b0[2], acc[i][3]+b0[3]);
        *(float4*)&g_P[(size_t)(bm + m0 + i) * HD + gn] = r;
    }
}

// ---------------------------------------------------------------------------
__device__ __forceinline__ void grid_arrive(unsigned* c) {
    __threadfence();
    __syncthreads();
    if (threadIdx.x == 0) atomicAdd(c, 1u);
}
__device__ __forceinline__ void grid_wait(unsigned* c, unsigned target) {
    if (threadIdx.x == 0) {
        while (*((volatile unsigned*)c) < target) __nanosleep(16);
        __threadfence();
    }
    __syncthreads();
}

// warp GEMM slice: 2 M-tiles (mbase..mbase+1), K slice kb0..kb0+8, depth-2 A
// prefetch. D[ui=mi*2+nf][4], 3-term bf16 hi/lo.
__device__ __forceinline__ void gemm_acc(float (&D)[4][4],
    const u64* __restrict__ ghHi, const u64* __restrict__ ghLo,
    const u64* __restrict__ sBhi, int kb0, int mbase, int gg, int tg)
{
    uint2 Ah01[3][2], Ah23[3][2], Al01[3][2], Al23[3][2];
#pragma unroll
    for (int p = 0; p < 2; p++)
#pragma unroll
        for (int mi = 0; mi < 2; mi++) {
            const size_t b = ((size_t)((mbase+mi)*64 + kb0 + p) << 6) + (gg<<3) + tg;
            Ah01[p][mi] = ldcg2(ghHi+b);  Ah23[p][mi] = ldcg2(ghHi+b+4);
            Al01[p][mi] = ldcg2(ghLo+b);  Al23[p][mi] = ldcg2(ghLo+b+4);
        }
#pragma unroll
    for (int j = 0; j < 8; j++) {
        if (j + 2 < 8) {
            const int s = (j + 2) % 3;
#pragma unroll
            for (int mi = 0; mi < 2; mi++) {
                const size_t b = ((size_t)((mbase+mi)*64 + kb0 + j + 2) << 6) + (gg<<3) + tg;
                Ah01[s][mi] = ldcg2(ghHi+b);  Ah23[s][mi] = ldcg2(ghHi+b+4);
                Al01[s][mi] = ldcg2(ghLo+b);  Al23[s][mi] = ldcg2(ghLo+b+4);
            }
        }
        const int c = j % 3;
        const int bi = ((kb0 + j) << 5) + (gg << 2) + tg;
        const uint2 Bh0 = *(const uint2*)(sBhi + bi);
        const uint2 Bh1 = *(const uint2*)(sBhi + 2048 + bi);
        const uint2 Bl0 = *(const uint2*)(sBhi + SB_ENT + bi);
        const uint2 Bl1 = *(const uint2*)(sBhi + SB_ENT + 2048 + bi);
#pragma unroll
        for (int mi = 0; mi < 2; mi++) {
            mma16816(D[mi*2+0], Ah01[c][mi], Ah23[c][mi], Bh0);
            mma16816(D[mi*2+0], Ah01[c][mi], Ah23[c][mi], Bl0);
            mma16816(D[mi*2+0], Al01[c][mi], Al23[c][mi], Bh0);
            mma16816(D[mi*2+1], Ah01[c][mi], Ah23[c][mi], Bh1);
            mma16816(D[mi*2+1], Ah01[c][mi], Ah23[c][mi], Bl1);
            mma16816(D[mi*2+1], Al01[c][mi], Al23[c][mi], Bh1);
        }
    }
}

// write 4 unit-partials into swizzled sred (all 16 warps)
__device__ __forceinline__ void kredw(const float (&D)[4][4], float* sred,
                                      int kw, int mbase, int lane)
{
    const int sw = lane & 7;
#pragma unroll
    for (int ui = 0; ui < 4; ui++) {
        const int u = (mbase + (ui >> 1)) * 2 + (ui & 1);
        float4* p = (float4*)&sred[((((u*32+lane) << 3) + (kw ^ sw)) << 2)];
        *p = make_float4(D[ui][0], D[ui][1], D[ui][2], D[ui][3]);
    }
}
// reduce unit u over 8 K-warps (warps 0-7 only)
__device__ __forceinline__ void kredr(const float* sred, int u, int lane, float r[4]) {
    const int sw = lane & 7;
    r[0] = r[1] = r[2] = r[3] = 0.f;
#pragma unroll
    for (int w = 0; w < 8; w++) {
        float4 v = *(const float4*)&sred[((((u*32+lane) << 3) + (w ^ sw)) << 2)];
        r[0] += v.x; r[1] += v.y; r[2] += v.z; r[3] += v.w;
    }
}

// ---------------------------------------------------------------------------
__global__ __launch_bounds__(TPB)
void rnn_recurrent_kernel(const float* __restrict__ bi1,
                          const float* __restrict__ bh1,
                          float* __restrict__ out,
                          int write_final)
{
    extern __shared__ u64 smem_u64[];
    u64*   sB   = smem_u64;                        // 6 x SB_ENT
    float* sred = (float*)(smem_u64 + 6*SB_ENT);   // 8192 f32

    const int tid  = threadIdx.x;
    const int wid  = tid >> 5;
    const int lane = tid & 31;
    const int gg   = lane >> 2;
    const int tg   = lane & 3;
    const int cta  = blockIdx.x;
    const int wh   = wid & 1;          // M half
    const int kw   = wid >> 1;         // K slice 0..7
    const int kb0  = kw * 8;
    const int mbase = wh * 2;

#pragma unroll
    for (int mp = 0; mp < 6; mp++) {
        const u64* src = g_Wp[mp >> 1][mp & 1] + (size_t)cta * SB_ENT;
        u64* dst = sB + mp * SB_ENT;
        for (int i = tid * 2; i < SB_ENT; i += TPB * 2)
            *(uint4*)(dst + i) = *(const uint4*)(src + i);
    }

    // epilogue coords (warps 0-7): unit u = wid
    const int u  = wid & 7;
    const int mt = u >> 1, nf = u & 1;
    const int m0 = mt * 16 + gg;
    const int n0 = cta * 16 + nf * 8 + tg * 2;
    const unsigned ei = (unsigned)((mt * 64 + cta) << 6) + (gg << 3) + (nf * 4 + tg);
    const float bias0 = bi1[n0] + bh1[n0];
    const float bias1 = bi1[n0+1] + bh1[n0+1];
    __syncthreads();

    float D[4][4], r[4];
    for (int t = 0; t < SEQ; t++) {
        const int rb = t & 1, wb = rb ^ 1;
        const int last = (t == SEQ - 1);

#pragma unroll
        for (int ui = 0; ui < 4; ui++)
            D[ui][0] = D[ui][1] = D[ui][2] = D[ui][3] = 0.f;

        // ---- layer 1: Wh0 x h1p ----
        gemm_acc(D, g_h1hi[rb], g_h1lo[rb], sB, kb0, mbase, gg, tg);
        kredw(D, sred, kw, mbase, lane);
        __syncthreads();
        if (wid < 8) {
            kredr(sred, u, lane, r);
            const float* Pt = g_P + (size_t)t * BATCH * HD;
            const float2 p0 = __ldg((const float2*)(Pt + (size_t)m0 * HD + n0));
            const float2 p1 = __ldg((const float2*)(Pt + (size_t)(m0+8) * HD + n0));
            float v0 = tanhf(r[0] + p0.x), v1 = tanhf(r[1] + p0.y);
            float v2 = tanhf(r[2] + p1.x), v3 = tanhf(r[3] + p1.y);
            u64 hi, lo; pack_hilo(v0, v1, v2, v3, hi, lo);
            stcg64(&g_h1hi[wb][ei], hi);
            stcg64(&g_h1lo[wb][ei], lo);
            if (write_final && last) {
                *(float2*)&out[OUT_MAIN + (size_t)m0*HD + n0]     = make_float2(v0, v1);
                *(float2*)&out[OUT_MAIN + (size_t)(m0+8)*HD + n0] = make_float2(v2, v3);
            }
        }
        grid_arrive(&g_c1);                        // publish h1(t)

        grid_wait(&g_c2, (unsigned)t * NCTA);      // h2p globally visible

#pragma unroll
        for (int ui = 0; ui < 4; ui++)
            D[ui][0] = D[ui][1] = D[ui][2] = D[ui][3] = 0.f;

        // ---- layer 2a: Wh1 x h2p (overlaps c1 wait) ----
        gemm_acc(D, g_h2hi[rb], g_h2lo[rb], sB + 4*SB_ENT, kb0, mbase, gg, tg);

        grid_wait(&g_c1, (unsigned)(t + 1) * NCTA); // h1(t) globally visible

        // ---- layer 2b: Wi1 x h1(t), same accumulator ----
        gemm_acc(D, g_h1hi[wb], g_h1lo[wb], sB + 2*SB_ENT, kb0, mbase, gg, tg);
        kredw(D, sred, kw, mbase, lane);
        __syncthreads();
        if (wid < 8) {
            kredr(sred, u, lane, r);
            float v0 = tanhf(r[0] + bias0), v1 = tanhf(r[1] + bias1);
            float v2 = tanhf(r[2] + bias0), v3 = tanhf(r[3] + bias1);
            u64 hi, lo; pack_hilo(v0, v1, v2, v3, hi, lo);
            stcg64(&g_h2hi[wb][ei], hi);
            stcg64(&g_h2lo[wb][ei], lo);
            float* ot = out + (size_t)t * BATCH * HD;
            *(float2*)&ot[(size_t)m0*HD + n0]     = make_float2(v0, v1);
            *(float2*)&ot[(size_t)(m0+8)*HD + n0] = make_float2(v2, v3);
            if (write_final && last) {
                float* hf = out + OUT_MAIN + (size_t)BATCH*HD;
                *(float2*)&hf[(size_t)m0*HD + n0]     = make_float2(v0, v1);
                *(float2*)&hf[(size_t)(m0+8)*HD + n0] = make_float2(v2, v3);
            }
        }
        grid_arrive(&g_c2);                        // publish h2(t)
    }
}

// ---------------------------------------------------------------------------
extern "C" void kernel_launch(void* const* d_in, const int* in_sizes, int n_in,
                              void* d_out, int out_size) {
    const float* x   = (const float*)d_in[0];
    const float* Wi0 = (const float*)d_in[1];
    const float* bi0 = (const float*)d_in[2];
    const float* Wh0 = (const float*)d_in[3];
    const float* bh0 = (const float*)d_in[4];
    const float* Wi1 = (const float*)d_in[5];
    const float* bi1 = (const float*)d_in[6];
    const float* Wh1 = (const float*)d_in[7];
    const float* bh1 = (const float*)d_in[8];
    float* out = (float*)d_out;

    const int write_final =
        ((size_t)out_size >= OUT_MAIN + (size_t)2 * BATCH * HD) ? 1 : 0;

    cudaFuncSetAttribute(rnn_recurrent_kernel,
                         cudaFuncAttributeMaxDynamicSharedMemorySize, SMEM_BYTES);

    rnn_reset_kernel<<<256, 256>>>();
    rnn_prepw_kernel<<<(3*GW_ENT + 255)/256, 256>>>(Wh0, Wi1, Wh1);
    rnn_precompute_kernel<<<dim3(HD/64, MTOT/64), 256>>>(x, Wi0, bi0, bh0);
    rnn_recurrent_kernel<<<NCTA, TPB, SMEM_BYTES>>>(bi1, bh1, out, write_final);
}

// round 8
// speedup vs baseline: 2.8469x; 1.1091x over previous
#include <cuda_runtime.h>
#include <cuda_bf16.h>
#include <math.h>
#include <stdint.h>

#define SEQ   512
#define BATCH 64
#define HD    1024
#define OUT_MAIN ((size_t)SEQ*BATCH*HD)
#define NCTA 64
#define TPB  512

typedef unsigned long long u64;

#define GH_ENT 16384                    // packed h: [mt4][kb64][g8][c8]
#define GW_ENT 262144                   // packed W: [nfg128][kb64][g8][tg4]
#define GX_ENT 8388608                  // packed x: [mt2048][kb64][g8][c8]
#define SB_ENT 4096
#define SMEM_BYTES (6*SB_ENT*8 + 32768)
#define PC_SMEM (8192*8)                // precompute: 2 bufs x 4096 entries

__device__ float g_P[33554432];
__device__ u64 g_h1hi[2][GH_ENT], g_h1lo[2][GH_ENT];
__device__ u64 g_h2hi[2][GH_ENT], g_h2lo[2][GH_ENT];
__device__ u64 g_Wp[3][2][GW_ENT];      // [Wh0,Wi1,Wh1][hi,lo]
__device__ u64 g_Wih[GW_ENT], g_Wil[GW_ENT];   // Wi0 packed
__device__ u64 g_xph[GX_ENT], g_xpl[GX_ENT];   // x packed
__device__ unsigned g_c1, g_c2;

__device__ __forceinline__ uint2 ldcg2(const u64* p) {
    uint2 v;
    asm volatile("ld.global.cg.v2.u32 {%0,%1},[%2];" : "=r"(v.x), "=r"(v.y) : "l"(p));
    return v;
}
__device__ __forceinline__ void stcg64(u64* p, u64 v) {
    asm volatile("st.global.cg.u64 [%0],%1;" :: "l"(p), "l"(v));
}
__device__ __forceinline__ void mma16816(float d[4], uint2 a01, uint2 a23, uint2 b) {
    asm volatile(
        "mma.sync.aligned.m16n8k16.row.col.f32.bf16.bf16.f32 "
        "{%0,%1,%2,%3},{%4,%5,%6,%7},{%8,%9},{%0,%1,%2,%3};"
        : "+f"(d[0]), "+f"(d[1]), "+f"(d[2]), "+f"(d[3])
        : "r"(a01.x), "r"(a01.y), "r"(a23.x), "r"(a23.y), "r"(b.x), "r"(b.y));
}
__device__ __forceinline__ unsigned short bfu(float x) {
    return __bfloat16_as_ushort(__float2bfloat16(x));
}
__device__ __forceinline__ void pack_hilo(float v0, float v1, float v2, float v3,
                                          u64& hi, u64& lo) {
    unsigned short h0 = bfu(v0), h1 = bfu(v1), h2 = bfu(v2), h3 = bfu(v3);
    unsigned short l0 = bfu(v0 - __bfloat162float(__ushort_as_bfloat16(h0)));
    unsigned short l1 = bfu(v1 - __bfloat162float(__ushort_as_bfloat16(h1)));
    unsigned short l2 = bfu(v2 - __bfloat162float(__ushort_as_bfloat16(h2)));
    unsigned short l3 = bfu(v3 - __bfloat162float(__ushort_as_bfloat16(h3)));
    hi = (u64)h0 | ((u64)h1 << 16) | ((u64)h2 << 32) | ((u64)h3 << 48);
    lo = (u64)l0 | ((u64)l1 << 16) | ((u64)l2 << 32) | ((u64)l3 << 48);
}

// ---------------------------------------------------------------------------
__global__ void rnn_reset_kernel() {
    unsigned idx = blockIdx.x * blockDim.x + threadIdx.x;
    if (idx == 0) { g_c1 = 0u; g_c2 = 0u; }
    if (idx < GH_ENT) {
        g_h1hi[0][idx] = 0ull; g_h1lo[0][idx] = 0ull;
        g_h2hi[0][idx] = 0ull; g_h2lo[0][idx] = 0ull;
    }
}

// pack 4 weight matrices into B-fragment hi/lo layout
__global__ __launch_bounds__(256)
void rnn_prepw_kernel(const float* __restrict__ Wh0, const float* __restrict__ Wi1,
                      const float* __restrict__ Wh1, const float* __restrict__ Wi0)
{
    unsigned idx = blockIdx.x * blockDim.x + threadIdx.x;
    if (idx >= 4u * GW_ENT) return;
    const int m = idx / GW_ENT;
    const unsigned e = idx % GW_ENT;
    const int nfg = e >> 11, kb = (e >> 5) & 63, gg = (e >> 2) & 7, tg = e & 3;
    const float* W = (m == 0) ? Wh0 : (m == 1) ? Wi1 : (m == 2) ? Wh1 : Wi0;
    const float* p = W + (size_t)(nfg * 8 + gg) * HD + kb * 16 + tg * 2;
    u64 hi, lo;
    pack_hilo(p[0], p[1], p[8], p[9], hi, lo);
    if (m < 3) { g_Wp[m][0][e] = hi; g_Wp[m][1][e] = lo; }
    else       { g_Wih[e] = hi;      g_Wil[e] = lo; }
}

// pack x into A-fragment hi/lo layout
__global__ __launch_bounds__(256)
void rnn_xpack_kernel(const float* __restrict__ X)
{
    unsigned e = blockIdx.x * blockDim.x + threadIdx.x;
    if (e >= GX_ENT) return;
    const int c = e & 7, gg = (e >> 3) & 7, kb = (e >> 6) & 63, mt = e >> 12;
    const int k = kb * 16 + ((c < 4) ? c * 2 : 8 + (c - 4) * 2);
    const int r0 = mt * 16 + gg;
    const float2 v01 = *(const float2*)&X[(size_t)r0 * HD + k];
    const float2 v23 = *(const float2*)&X[(size_t)(r0 + 8) * HD + k];
    u64 hi, lo;
    pack_hilo(v01.x, v01.y, v23.x, v23.y, hi, lo);
    g_xph[e] = hi; g_xpl[e] = lo;
}

// ---------------------------------------------------------------------------
// precompute via bf16-pair MMA: P = x@Wi0^T + bi0 + bh0
// grid (16 n-tiles, 256 m-tiles); CTA 256 thr; warp w owns m-subtile
// ---------------------------------------------------------------------------
__device__ __forceinline__ void pc_stageB(u64* sbase, int ntile, int ch, int tid) {
#pragma unroll
    for (int i = 0; i < 8; i++) {
        const int u = tid + i * 256;
        const int prec = u >> 10, r = u & 1023, nfg = r >> 7, off = (r & 127) * 2;
        const u64* src = (prec ? g_Wil : g_Wih)
                       + ((size_t)(ntile * 8 + nfg) * 64 + ch * 8) * 32 + off;
        unsigned ds = (unsigned)__cvta_generic_to_shared(
            sbase + prec * 2048 + nfg * 256 + off);
        asm volatile("cp.async.cg.shared.global [%0],[%1],16;" :: "r"(ds), "l"(src));
    }
}

__global__ __launch_bounds__(256)
void rnn_precompute_mma(const float* __restrict__ bi0, const float* __restrict__ bh0)
{
    extern __shared__ u64 sB[];                    // 2 x 4096 entries
    const int tid = threadIdx.x, wid = tid >> 5, lane = tid & 31;
    const int gg = lane >> 2, tg = lane & 3;
    const int ntile = blockIdx.x;
    const int mt_g = blockIdx.y * 8 + wid;

    float D[8][4];
#pragma unroll
    for (int nf = 0; nf < 8; nf++)
        D[nf][0] = D[nf][1] = D[nf][2] = D[nf][3] = 0.f;

    pc_stageB(sB, ntile, 0, tid);
    asm volatile("cp.async.commit_group;" ::: "memory");

    uint2 Ah01[3], Ah23[3], Al01[3], Al23[3];
#define PCLOADA(s, kb) { \
    const size_t b_ = ((size_t)(mt_g * 64 + (kb)) << 6) + (gg << 3) + tg; \
    Ah01[s] = ldcg2(g_xph + b_); Ah23[s] = ldcg2(g_xph + b_ + 4); \
    Al01[s] = ldcg2(g_xpl + b_); Al23[s] = ldcg2(g_xpl + b_ + 4); }
    PCLOADA(0, 0); PCLOADA(1, 1);

    for (int ch = 0; ch < 8; ch++) {
        if (ch + 1 < 8) {
            pc_stageB(sB + ((ch + 1) & 1) * 4096, ntile, ch + 1, tid);
            asm volatile("cp.async.commit_group;" ::: "memory");
            asm volatile("cp.async.wait_group 1;" ::: "memory");
        } else {
            asm volatile("cp.async.wait_group 0;" ::: "memory");
        }
        __syncthreads();
        const u64* bufp = sB + (ch & 1) * 4096;
#pragma unroll
        for (int kl = 0; kl < 8; kl++) {
            const int kb = ch * 8 + kl;
            if (kb + 2 < 64) PCLOADA((kb + 2) % 3, kb + 2);
            const int c = kb % 3;
            uint2 Bh[8], Bl[8];
#pragma unroll
            for (int nf = 0; nf < 8; nf++) {
                Bh[nf] = *(const uint2*)(bufp + nf * 256 + kl * 32 + lane);
                Bl[nf] = *(const uint2*)(bufp + 2048 + nf * 256 + kl * 32 + lane);
            }
#pragma unroll
            for (int nf = 0; nf < 8; nf++) mma16816(D[nf], Ah01[c], Ah23[c], Bh[nf]);
#pragma unroll
            for (int nf = 0; nf < 8; nf++) mma16816(D[nf], Ah01[c], Ah23[c], Bl[nf]);
#pragma unroll
            for (int nf = 0; nf < 8; nf++) mma16816(D[nf], Al01[c], Al23[c], Bh[nf]);
        }
        __syncthreads();
    }
#undef PCLOADA

    const int r0 = mt_g * 16 + gg;
#pragma unroll
    for (int nf = 0; nf < 8; nf++) {
        const int n0 = ntile * 64 + nf * 8 + tg * 2;
        const float b0 = bi0[n0] + bh0[n0], b1 = bi0[n0 + 1] + bh0[n0 + 1];
        *(float2*)&g_P[(size_t)r0 * HD + n0]       = make_float2(D[nf][0] + b0, D[nf][1] + b1);
        *(float2*)&g_P[(size_t)(r0 + 8) * HD + n0] = make_float2(D[nf][2] + b0, D[nf][3] + b1);
    }
}

// ---------------------------------------------------------------------------
__device__ __forceinline__ void grid_arrive(unsigned* c) {
    __threadfence();
    __syncthreads();
    if (threadIdx.x == 0) atomicAdd(c, 1u);
}
__device__ __forceinline__ void grid_wait(unsigned* c, unsigned target) {
    if (threadIdx.x == 0) {
        while (*((volatile unsigned*)c) < target) __nanosleep(16);
        __threadfence();
    }
    __syncthreads();
}

// warp GEMM slice: A depth-2 (3-slot) prefetch, B register double-buffer,
// term-major MMA order (accumulator chains spaced by 4).
__device__ __forceinline__ void gemm_acc(float (&D)[4][4],
    const u64* __restrict__ ghHi, const u64* __restrict__ ghLo,
    const u64* __restrict__ sBhi, int kb0, int mbase, int gg, int tg)
{
    uint2 Ah01[3][2], Ah23[3][2], Al01[3][2], Al23[3][2];
#pragma unroll
    for (int p = 0; p < 2; p++)
#pragma unroll
        for (int mi = 0; mi < 2; mi++) {
            const size_t b = ((size_t)((mbase+mi)*64 + kb0 + p) << 6) + (gg<<3) + tg;
            Ah01[p][mi] = ldcg2(ghHi+b);  Ah23[p][mi] = ldcg2(ghHi+b+4);
            Al01[p][mi] = ldcg2(ghLo+b);  Al23[p][mi] = ldcg2(ghLo+b+4);
        }
    uint2 Bh0[2], Bh1[2], Bl0[2], Bl1[2];
    {
        const int bi = (kb0 << 5) + (gg << 2) + tg;
        Bh0[0] = *(const uint2*)(sBhi + bi);
        Bh1[0] = *(const uint2*)(sBhi + 2048 + bi);
        Bl0[0] = *(const uint2*)(sBhi + SB_ENT + bi);
        Bl1[0] = *(const uint2*)(sBhi + SB_ENT + 2048 + bi);
    }
#pragma unroll
    for (int j = 0; j < 8; j++) {
        const int cb = j & 1, nb = cb ^ 1;
        if (j < 7) {
            const int bi = ((kb0 + j + 1) << 5) + (gg << 2) + tg;
            Bh0[nb] = *(const uint2*)(sBhi + bi);
            Bh1[nb] = *(const uint2*)(sBhi + 2048 + bi);
            Bl0[nb] = *(const uint2*)(sBhi + SB_ENT + bi);
            Bl1[nb] = *(const uint2*)(sBhi + SB_ENT + 2048 + bi);
        }
        if (j + 2 < 8) {
            const int s = (j + 2) % 3;
#pragma unroll
            for (int mi = 0; mi < 2; mi++) {
                const size_t b = ((size_t)((mbase+mi)*64 + kb0 + j + 2) << 6) + (gg<<3) + tg;
                Ah01[s][mi] = ldcg2(ghHi+b);  Ah23[s][mi] = ldcg2(ghHi+b+4);
                Al01[s][mi] = ldcg2(ghLo+b);  Al23[s][mi] = ldcg2(ghLo+b+4);
            }
        }
        const int c = j % 3;
        mma16816(D[0], Ah01[c][0], Ah23[c][0], Bh0[cb]);
        mma16816(D[1], Ah01[c][0], Ah23[c][0], Bh1[cb]);
        mma16816(D[2], Ah01[c][1], Ah23[c][1], Bh0[cb]);
        mma16816(D[3], Ah01[c][1], Ah23[c][1], Bh1[cb]);
        mma16816(D[0], Ah01[c][0], Ah23[c][0], Bl0[cb]);
        mma16816(D[1], Ah01[c][0], Ah23[c][0], Bl1[cb]);
        mma16816(D[2], Ah01[c][1], Ah23[c][1], Bl0[cb]);
        mma16816(D[3], Ah01[c][1], Ah23[c][1], Bl1[cb]);
        mma16816(D[0], Al01[c][0], Al23[c][0], Bh0[cb]);
        mma16816(D[1], Al01[c][0], Al23[c][0], Bh1[cb]);
        mma16816(D[2], Al01[c][1], Al23[c][1], Bh0[cb]);
        mma16816(D[3], Al01[c][1], Al23[c][1], Bh1[cb]);
    }
}

__device__ __forceinline__ void kredw(const float (&D)[4][4], float* sred,
                                      int kw, int mbase, int lane)
{
    const int sw = lane & 7;
#pragma unroll
    for (int ui = 0; ui < 4; ui++) {
        const int u = (mbase + (ui >> 1)) * 2 + (ui & 1);
        float4* p = (float4*)&sred[((((u*32+lane) << 3) + (kw ^ sw)) << 2)];
        *p = make_float4(D[ui][0], D[ui][1], D[ui][2], D[ui][3]);
    }
}
__device__ __forceinline__ void kredr(const float* sred, int u, int lane, float r[4]) {
    const int sw = lane & 7;
    r[0] = r[1] = r[2] = r[3] = 0.f;
#pragma unroll
    for (int w = 0; w < 8; w++) {
        float4 v = *(const float4*)&sred[((((u*32+lane) << 3) + (w ^ sw)) << 2)];
        r[0] += v.x; r[1] += v.y; r[2] += v.z; r[3] += v.w;
    }
}

// ---------------------------------------------------------------------------
__global__ __launch_bounds__(TPB)
void rnn_recurrent_kernel(const float* __restrict__ bi1,
                          const float* __restrict__ bh1,
                          float* __restrict__ out,
                          int write_final)
{
    extern __shared__ u64 smem_u64[];
    u64*   sB   = smem_u64;
    float* sred = (float*)(smem_u64 + 6*SB_ENT);

    const int tid  = threadIdx.x;
    const int wid  = tid >> 5;
    const int lane = tid & 31;
    const int gg   = lane >> 2;
    const int tg   = lane & 3;
    const int cta  = blockIdx.x;
    const int wh   = wid & 1;
    const int kw   = wid >> 1;
    const int kb0  = kw * 8;
    const int mbase = wh * 2;

#pragma unroll
    for (int mp = 0; mp < 6; mp++) {
        const u64* src = g_Wp[mp >> 1][mp & 1] + (size_t)cta * SB_ENT;
        u64* dst = sB + mp * SB_ENT;
        for (int i = tid * 2; i < SB_ENT; i += TPB * 2)
            *(uint4*)(dst + i) = *(const uint4*)(src + i);
    }

    const int u  = wid & 7;
    const int mt = u >> 1, nf = u & 1;
    const int m0 = mt * 16 + gg;
    const int n0 = cta * 16 + nf * 8 + tg * 2;
    const unsigned ei = (unsigned)((mt * 64 + cta) << 6) + (gg << 3) + (nf * 4 + tg);
    const float bias0 = bi1[n0] + bh1[n0];
    const float bias1 = bi1[n0+1] + bh1[n0+1];
    __syncthreads();

    float D[4][4], r[4];
    for (int t = 0; t < SEQ; t++) {
        const int rb = t & 1, wb = rb ^ 1;
        const int last = (t == SEQ - 1);

#pragma unroll
        for (int ui = 0; ui < 4; ui++)
            D[ui][0] = D[ui][1] = D[ui][2] = D[ui][3] = 0.f;

        // ---- layer 1: Wh0 x h1p ----
        gemm_acc(D, g_h1hi[rb], g_h1lo[rb], sB, kb0, mbase, gg, tg);
        kredw(D, sred, kw, mbase, lane);
        __syncthreads();
        if (wid < 8) {
            kredr(sred, u, lane, r);
            const float* Pt = g_P + (size_t)t * BATCH * HD;
            const float2 p0 = __ldg((const float2*)(Pt + (size_t)m0 * HD + n0));
            const float2 p1 = __ldg((const float2*)(Pt + (size_t)(m0+8) * HD + n0));
            float v0 = tanhf(r[0] + p0.x), v1 = tanhf(r[1] + p0.y);
            float v2 = tanhf(r[2] + p1.x), v3 = tanhf(r[3] + p1.y);
            u64 hi, lo; pack_hilo(v0, v1, v2, v3, hi, lo);
            stcg64(&g_h1hi[wb][ei], hi);
            stcg64(&g_h1lo[wb][ei], lo);
            if (write_final && last) {
                *(float2*)&out[OUT_MAIN + (size_t)m0*HD + n0]     = make_float2(v0, v1);
                *(float2*)&out[OUT_MAIN + (size_t)(m0+8)*HD + n0] = make_float2(v2, v3);
            }
        }
        grid_arrive(&g_c1);

        grid_wait(&g_c2, (unsigned)t * NCTA);

#pragma unroll
        for (int ui = 0; ui < 4; ui++)
            D[ui][0] = D[ui][1] = D[ui][2] = D[ui][3] = 0.f;

        // ---- layer 2a: Wh1 x h2p ----
        gemm_acc(D, g_h2hi[rb], g_h2lo[rb], sB + 4*SB_ENT, kb0, mbase, gg, tg);

        grid_wait(&g_c1, (unsigned)(t + 1) * NCTA);

        // ---- layer 2b: Wi1 x h1(t) ----
        gemm_acc(D, g_h1hi[wb], g_h1lo[wb], sB + 2*SB_ENT, kb0, mbase, gg, tg);
        kredw(D, sred, kw, mbase, lane);
        __syncthreads();
        if (wid < 8) {
            kredr(sred, u, lane, r);
            float v0 = tanhf(r[0] + bias0), v1 = tanhf(r[1] + bias1);
            float v2 = tanhf(r[2] + bias0), v3 = tanhf(r[3] + bias1);
            u64 hi, lo; pack_hilo(v0, v1, v2, v3, hi, lo);
            stcg64(&g_h2hi[wb][ei], hi);
            stcg64(&g_h2lo[wb][ei], lo);
            float* ot = out + (size_t)t * BATCH * HD;
            *(float2*)&ot[(size_t)m0*HD + n0]     = make_float2(v0, v1);
            *(float2*)&ot[(size_t)(m0+8)*HD + n0] = make_float2(v2, v3);
            if (write_final && last) {
                float* hf = out + OUT_MAIN + (size_t)BATCH*HD;
                *(float2*)&hf[(size_t)m0*HD + n0]     = make_float2(v0, v1);
                *(float2*)&hf[(size_t)(m0+8)*HD + n0] = make_float2(v2, v3);
            }
        }
        grid_arrive(&g_c2);
    }
}

// ---------------------------------------------------------------------------
extern "C" void kernel_launch(void* const* d_in, const int* in_sizes, int n_in,
                              void* d_out, int out_size) {
    const float* x   = (const float*)d_in[0];
    const float* Wi0 = (const float*)d_in[1];
    const float* bi0 = (const float*)d_in[2];
    const float* Wh0 = (const float*)d_in[3];
    const float* bh0 = (const float*)d_in[4];
    const float* Wi1 = (const float*)d_in[5];
    const float* bi1 = (const float*)d_in[6];
    const float* Wh1 = (const float*)d_in[7];
    const float* bh1 = (const float*)d_in[8];
    float* out = (float*)d_out;

    const int write_final =
        ((size_t)out_size >= OUT_MAIN + (size_t)2 * BATCH * HD) ? 1 : 0;

    cudaFuncSetAttribute(rnn_recurrent_kernel,
                         cudaFuncAttributeMaxDynamicSharedMemorySize, SMEM_BYTES);
    cudaFuncSetAttribute(rnn_precompute_mma,
                         cudaFuncAttributeMaxDynamicSharedMemorySize, PC_SMEM);

    rnn_reset_kernel<<<256, 256>>>();
    rnn_prepw_kernel<<<(4*GW_ENT + 255)/256, 256>>>(Wh0, Wi1, Wh1, Wi0);
    rnn_xpack_kernel<<<(GX_ENT + 255)/256, 256>>>(x);
    rnn_precompute_mma<<<dim3(16, 256), 256, PC_SMEM>>>(bi0, bh0);
    rnn_recurrent_kernel<<<NCTA, TPB, SMEM_BYTES>>>(bi1, bh1, out, write_final);
}

// round 9
// speedup vs baseline: 3.7092x; 1.3029x over previous
#include <cuda_runtime.h>
#include <cuda_bf16.h>
#include <math.h>
#include <stdint.h>

#define SEQ   512
#define BATCH 64
#define HD    1024
#define OUT_MAIN ((size_t)SEQ*BATCH*HD)
#define NG    64                        // CTAs per pipeline group
#define TPB   512

typedef unsigned long long u64;

#define GH_ENT 16384                    // packed h: [mt4][kb64][g8][c8]
#define GW_ENT 262144                   // packed W: [nfg128][kb64][g8][tg4]
#define GX_ENT 8388608                  // packed x
#define SB_ENT 4096
#define SMEM2_BYTES (4*SB_ENT*8 + 32768)   // 163840: 2 matrices + sred
#define PC_SMEM (8192*8)

__device__ float g_P[33554432];
__device__ u64 g_h1hi[2][GH_ENT], g_h1lo[2][GH_ENT];
__device__ u64 g_h2hi[2][GH_ENT], g_h2lo[2][GH_ENT];
__device__ u64 g_Wp[3][2][GW_ENT];      // [Wh0,Wi1,Wh1][hi,lo]
__device__ u64 g_Wih[GW_ENT], g_Wil[GW_ENT];
__device__ u64 g_xph[GX_ENT], g_xpl[GX_ENT];
__device__ unsigned g_c1, g_c2, g_c3, g_c4;

__device__ __forceinline__ uint2 ldcg2(const u64* p) {
    uint2 v;
    asm volatile("ld.global.cg.v2.u32 {%0,%1},[%2];" : "=r"(v.x), "=r"(v.y) : "l"(p));
    return v;
}
__device__ __forceinline__ void stcg64(u64* p, u64 v) {
    asm volatile("st.global.cg.u64 [%0],%1;" :: "l"(p), "l"(v));
}
__device__ __forceinline__ void mma16816(float d[4], uint2 a01, uint2 a23, uint2 b) {
    asm volatile(
        "mma.sync.aligned.m16n8k16.row.col.f32.bf16.bf16.f32 "
        "{%0,%1,%2,%3},{%4,%5,%6,%7},{%8,%9},{%0,%1,%2,%3};"
        : "+f"(d[0]), "+f"(d[1]), "+f"(d[2]), "+f"(d[3])
        : "r"(a01.x), "r"(a01.y), "r"(a23.x), "r"(a23.y), "r"(b.x), "r"(b.y));
}
__device__ __forceinline__ unsigned short bfu(float x) {
    return __bfloat16_as_ushort(__float2bfloat16(x));
}
__device__ __forceinline__ void pack_hilo(float v0, float v1, float v2, float v3,
                                          u64& hi, u64& lo) {
    unsigned short h0 = bfu(v0), h1 = bfu(v1), h2 = bfu(v2), h3 = bfu(v3);
    unsigned short l0 = bfu(v0 - __bfloat162float(__ushort_as_bfloat16(h0)));
    unsigned short l1 = bfu(v1 - __bfloat162float(__ushort_as_bfloat16(h1)));
    unsigned short l2 = bfu(v2 - __bfloat162float(__ushort_as_bfloat16(h2)));
    unsigned short l3 = bfu(v3 - __bfloat162float(__ushort_as_bfloat16(h3)));
    hi = (u64)h0 | ((u64)h1 << 16) | ((u64)h2 << 32) | ((u64)h3 << 48);
    lo = (u64)l0 | ((u64)l1 << 16) | ((u64)l2 << 32) | ((u64)l3 << 48);
}

// ---------------------------------------------------------------------------
__global__ void rnn_reset_kernel() {
    unsigned idx = blockIdx.x * blockDim.x + threadIdx.x;
    if (idx == 0) { g_c1 = 0u; g_c2 = 0u; g_c3 = 0u; g_c4 = 0u; }
    if (idx < GH_ENT) {
        g_h1hi[0][idx] = 0ull; g_h1lo[0][idx] = 0ull;
        g_h2hi[0][idx] = 0ull; g_h2lo[0][idx] = 0ull;
    }
}

__global__ __launch_bounds__(256)
void rnn_prepw_kernel(const float* __restrict__ Wh0, const float* __restrict__ Wi1,
                      const float* __restrict__ Wh1, const float* __restrict__ Wi0)
{
    unsigned idx = blockIdx.x * blockDim.x + threadIdx.x;
    if (idx >= 4u * GW_ENT) return;
    const int m = idx / GW_ENT;
    const unsigned e = idx % GW_ENT;
    const int nfg = e >> 11, kb = (e >> 5) & 63, gg = (e >> 2) & 7, tg = e & 3;
    const float* W = (m == 0) ? Wh0 : (m == 1) ? Wi1 : (m == 2) ? Wh1 : Wi0;
    const float* p = W + (size_t)(nfg * 8 + gg) * HD + kb * 16 + tg * 2;
    u64 hi, lo;
    pack_hilo(p[0], p[1], p[8], p[9], hi, lo);
    if (m < 3) { g_Wp[m][0][e] = hi; g_Wp[m][1][e] = lo; }
    else       { g_Wih[e] = hi;      g_Wil[e] = lo; }
}

__global__ __launch_bounds__(256)
void rnn_xpack_kernel(const float* __restrict__ X)
{
    unsigned e = blockIdx.x * blockDim.x + threadIdx.x;
    if (e >= GX_ENT) return;
    const int c = e & 7, gg = (e >> 3) & 7, kb = (e >> 6) & 63, mt = e >> 12;
    const int k = kb * 16 + ((c < 4) ? c * 2 : 8 + (c - 4) * 2);
    const int r0 = mt * 16 + gg;
    const float2 v01 = *(const float2*)&X[(size_t)r0 * HD + k];
    const float2 v23 = *(const float2*)&X[(size_t)(r0 + 8) * HD + k];
    u64 hi, lo;
    pack_hilo(v01.x, v01.y, v23.x, v23.y, hi, lo);
    g_xph[e] = hi; g_xpl[e] = lo;
}

// ---------------------------------------------------------------------------
// precompute via bf16-pair MMA (unchanged from R8)
// ---------------------------------------------------------------------------
__device__ __forceinline__ void pc_stageB(u64* sbase, int ntile, int ch, int tid) {
#pragma unroll
    for (int i = 0; i < 8; i++) {
        const int u = tid + i * 256;
        const int prec = u >> 10, r = u & 1023, nfg = r >> 7, off = (r & 127) * 2;
        const u64* src = (prec ? g_Wil : g_Wih)
                       + ((size_t)(ntile * 8 + nfg) * 64 + ch * 8) * 32 + off;
        unsigned ds = (unsigned)__cvta_generic_to_shared(
            sbase + prec * 2048 + nfg * 256 + off);
        asm volatile("cp.async.cg.shared.global [%0],[%1],16;" :: "r"(ds), "l"(src));
    }
}

__global__ __launch_bounds__(256)
void rnn_precompute_mma(const float* __restrict__ bi0, const float* __restrict__ bh0)
{
    extern __shared__ u64 sB[];
    const int tid = threadIdx.x, wid = tid >> 5, lane = tid & 31;
    const int gg = lane >> 2, tg = lane & 3;
    const int ntile = blockIdx.x;
    const int mt_g = blockIdx.y * 8 + wid;

    float D[8][4];
#pragma unroll
    for (int nf = 0; nf < 8; nf++)
        D[nf][0] = D[nf][1] = D[nf][2] = D[nf][3] = 0.f;

    pc_stageB(sB, ntile, 0, tid);
    asm volatile("cp.async.commit_group;" ::: "memory");

    uint2 Ah01[3], Ah23[3], Al01[3], Al23[3];
#define PCLOADA(s, kb) { \
    const size_t b_ = ((size_t)(mt_g * 64 + (kb)) << 6) + (gg << 3) + tg; \
    Ah01[s] = ldcg2(g_xph + b_); Ah23[s] = ldcg2(g_xph + b_ + 4); \
    Al01[s] = ldcg2(g_xpl + b_); Al23[s] = ldcg2(g_xpl + b_ + 4); }
    PCLOADA(0, 0); PCLOADA(1, 1);

    for (int ch = 0; ch < 8; ch++) {
        if (ch + 1 < 8) {
            pc_stageB(sB + ((ch + 1) & 1) * 4096, ntile, ch + 1, tid);
            asm volatile("cp.async.commit_group;" ::: "memory");
            asm volatile("cp.async.wait_group 1;" ::: "memory");
        } else {
            asm volatile("cp.async.wait_group 0;" ::: "memory");
        }
        __syncthreads();
        const u64* bufp = sB + (ch & 1) * 4096;
#pragma unroll
        for (int kl = 0; kl < 8; kl++) {
            const int kb = ch * 8 + kl;
            if (kb + 2 < 64) PCLOADA((kb + 2) % 3, kb + 2);
            const int c = kb % 3;
            uint2 Bh[8], Bl[8];
#pragma unroll
            for (int nf = 0; nf < 8; nf++) {
                Bh[nf] = *(const uint2*)(bufp + nf * 256 + kl * 32 + lane);
                Bl[nf] = *(const uint2*)(bufp + 2048 + nf * 256 + kl * 32 + lane);
            }
#pragma unroll
            for (int nf = 0; nf < 8; nf++) mma16816(D[nf], Ah01[c], Ah23[c], Bh[nf]);
#pragma unroll
            for (int nf = 0; nf < 8; nf++) mma16816(D[nf], Ah01[c], Ah23[c], Bl[nf]);
#pragma unroll
            for (int nf = 0; nf < 8; nf++) mma16816(D[nf], Al01[c], Al23[c], Bh[nf]);
        }
        __syncthreads();
    }
#undef PCLOADA

    const int r0 = mt_g * 16 + gg;
#pragma unroll
    for (int nf = 0; nf < 8; nf++) {
        const int n0 = ntile * 64 + nf * 8 + tg * 2;
        const float b0 = bi0[n0] + bh0[n0], b1 = bi0[n0 + 1] + bh0[n0 + 1];
        *(float2*)&g_P[(size_t)r0 * HD + n0]       = make_float2(D[nf][0] + b0, D[nf][1] + b1);
        *(float2*)&g_P[(size_t)(r0 + 8) * HD + n0] = make_float2(D[nf][2] + b0, D[nf][3] + b1);
    }
}

// ---------------------------------------------------------------------------
__device__ __forceinline__ void grid_arrive(unsigned* c) {
    __threadfence();
    __syncthreads();
    if (threadIdx.x == 0) atomicAdd(c, 1u);
}
__device__ __forceinline__ void grid_wait(unsigned* c, unsigned target) {
    if (threadIdx.x == 0) {
        while (*((volatile unsigned*)c) < target) __nanosleep(16);
        __threadfence();
    }
    __syncthreads();
}

// warp GEMM slice (unchanged from R8)
__device__ __forceinline__ void gemm_acc(float (&D)[4][4],
    const u64* __restrict__ ghHi, const u64* __restrict__ ghLo,
    const u64* __restrict__ sBhi, int kb0, int mbase, int gg, int tg)
{
    uint2 Ah01[3][2], Ah23[3][2], Al01[3][2], Al23[3][2];
#pragma unroll
    for (int p = 0; p < 2; p++)
#pragma unroll
        for (int mi = 0; mi < 2; mi++) {
            const size_t b = ((size_t)((mbase+mi)*64 + kb0 + p) << 6) + (gg<<3) + tg;
            Ah01[p][mi] = ldcg2(ghHi+b);  Ah23[p][mi] = ldcg2(ghHi+b+4);
            Al01[p][mi] = ldcg2(ghLo+b);  Al23[p][mi] = ldcg2(ghLo+b+4);
        }
    uint2 Bh0[2], Bh1[2], Bl0[2], Bl1[2];
    {
        const int bi = (kb0 << 5) + (gg << 2) + tg;
        Bh0[0] = *(const uint2*)(sBhi + bi);
        Bh1[0] = *(const uint2*)(sBhi + 2048 + bi);
        Bl0[0] = *(const uint2*)(sBhi + SB_ENT + bi);
        Bl1[0] = *(const uint2*)(sBhi + SB_ENT + 2048 + bi);
    }
#pragma unroll
    for (int j = 0; j < 8; j++) {
        const int cb = j & 1, nb = cb ^ 1;
        if (j < 7) {
            const int bi = ((kb0 + j + 1) << 5) + (gg << 2) + tg;
            Bh0[nb] = *(const uint2*)(sBhi + bi);
            Bh1[nb] = *(const uint2*)(sBhi + 2048 + bi);
            Bl0[nb] = *(const uint2*)(sBhi + SB_ENT + bi);
            Bl1[nb] = *(const uint2*)(sBhi + SB_ENT + 2048 + bi);
        }
        if (j + 2 < 8) {
            const int s = (j + 2) % 3;
#pragma unroll
            for (int mi = 0; mi < 2; mi++) {
                const size_t b = ((size_t)((mbase+mi)*64 + kb0 + j + 2) << 6) + (gg<<3) + tg;
                Ah01[s][mi] = ldcg2(ghHi+b);  Ah23[s][mi] = ldcg2(ghHi+b+4);
                Al01[s][mi] = ldcg2(ghLo+b);  Al23[s][mi] = ldcg2(ghLo+b+4);
            }
        }
        const int c = j % 3;
        mma16816(D[0], Ah01[c][0], Ah23[c][0], Bh0[cb]);
        mma16816(D[1], Ah01[c][0], Ah23[c][0], Bh1[cb]);
        mma16816(D[2], Ah01[c][1], Ah23[c][1], Bh0[cb]);
        mma16816(D[3], Ah01[c][1], Ah23[c][1], Bh1[cb]);
        mma16816(D[0], Ah01[c][0], Ah23[c][0], Bl0[cb]);
        mma16816(D[1], Ah01[c][0], Ah23[c][0], Bl1[cb]);
        mma16816(D[2], Ah01[c][1], Ah23[c][1], Bl0[cb]);
        mma16816(D[3], Ah01[c][1], Ah23[c][1], Bl1[cb]);
        mma16816(D[0], Al01[c][0], Al23[c][0], Bh0[cb]);
        mma16816(D[1], Al01[c][0], Al23[c][0], Bh1[cb]);
        mma16816(D[2], Al01[c][1], Al23[c][1], Bh0[cb]);
        mma16816(D[3], Al01[c][1], Al23[c][1], Bh1[cb]);
    }
}

__device__ __forceinline__ void kredw(const float (&D)[4][4], float* sred,
                                      int kw, int mbase, int lane)
{
    const int sw = lane & 7;
#pragma unroll
    for (int ui = 0; ui < 4; ui++) {
        const int u = (mbase + (ui >> 1)) * 2 + (ui & 1);
        float4* p = (float4*)&sred[((((u*32+lane) << 3) + (kw ^ sw)) << 2)];
        *p = make_float4(D[ui][0], D[ui][1], D[ui][2], D[ui][3]);
    }
}
__device__ __forceinline__ void kredr(const float* sred, int u, int lane, float r[4]) {
    const int sw = lane & 7;
    r[0] = r[1] = r[2] = r[3] = 0.f;
#pragma unroll
    for (int w = 0; w < 8; w++) {
        float4 v = *(const float4*)&sred[((((u*32+lane) << 3) + (w ^ sw)) << 2)];
        r[0] += v.x; r[1] += v.y; r[2] += v.z; r[3] += v.w;
    }
}

// ---------------------------------------------------------------------------
// pipeline-parallel recurrent kernel: group A (CTA 0-63) = W0/h1 chain;
// group B (CTA 64-127) = W2+W1/h2 chain.
// ---------------------------------------------------------------------------
__global__ __launch_bounds__(TPB)
void rnn_recurrent_kernel(const float* __restrict__ bi1,
                          const float* __restrict__ bh1,
                          float* __restrict__ out,
                          int write_final)
{
    extern __shared__ u64 smem_u64[];
    u64*   sB   = smem_u64;                        // 4 x SB_ENT
    float* sred = (float*)(smem_u64 + 4*SB_ENT);

    const int tid  = threadIdx.x;
    const int wid  = tid >> 5;
    const int lane = tid & 31;
    const int gg   = lane >> 2;
    const int tg   = lane & 3;
    const int grpB = (blockIdx.x >= NG);
    const int cta  = grpB ? (blockIdx.x - NG) : blockIdx.x;
    const int kw   = wid >> 1;
    const int kb0  = kw * 8;
    const int mbase = (wid & 1) * 2;

    // group A: sB[0..2SB)=Wh0(hi,lo). group B: sB[0..2SB)=Wi1, [2SB..4SB)=Wh1
#pragma unroll
    for (int mp = 0; mp < 4; mp++) {
        const int mat = grpB ? ((mp >> 1) + 1) : 0;
        if (!grpB && mp >= 2) break;
        const u64* src = g_Wp[mat][mp & 1] + (size_t)cta * SB_ENT;
        u64* dst = sB + ((grpB ? (mp >> 1) * 2 : 0) + (mp & 1)) * SB_ENT;
        for (int i = tid * 2; i < SB_ENT; i += TPB * 2)
            *(uint4*)(dst + i) = *(const uint4*)(src + i);
    }

    const int u  = wid & 7;
    const int mt = u >> 1, nf = u & 1;
    const int m0 = mt * 16 + gg;
    const int n0 = cta * 16 + nf * 8 + tg * 2;
    const unsigned ei = (unsigned)((mt * 64 + cta) << 6) + (gg << 3) + (nf * 4 + tg);
    const float bias0 = bi1[n0] + bh1[n0];
    const float bias1 = bi1[n0+1] + bh1[n0+1];
    __syncthreads();

    float D[4][4], r[4];

    if (!grpB) {
        // ---------------- group A: h1 chain (W0 only) ----------------
        for (int t = 0; t < SEQ; t++) {
            const int rb = t & 1, wb = rb ^ 1;
            grid_wait(&g_c1, (unsigned)t * NG);          // h1(t-1) visible
#pragma unroll
            for (int ui = 0; ui < 4; ui++)
                D[ui][0] = D[ui][1] = D[ui][2] = D[ui][3] = 0.f;
            gemm_acc(D, g_h1hi[rb], g_h1lo[rb], sB, kb0, mbase, gg, tg);
            kredw(D, sred, kw, mbase, lane);
            // B must be done reading h1 parity wb (its W1 of step t-2)
            grid_wait(&g_c3, (t >= 2) ? (unsigned)(t - 1) * NG : 0u);
            __syncthreads();
            if (wid < 8) {
                kredr(sred, u, lane, r);
                const float* Pt = g_P + (size_t)t * BATCH * HD;
                const float2 p0 = __ldg((const float2*)(Pt + (size_t)m0 * HD + n0));
                const float2 p1 = __ldg((const float2*)(Pt + (size_t)(m0+8) * HD + n0));
                float v0 = tanhf(r[0] + p0.x), v1 = tanhf(r[1] + p0.y);
                float v2 = tanhf(r[2] + p1.x), v3 = tanhf(r[3] + p1.y);
                u64 hi, lo; pack_hilo(v0, v1, v2, v3, hi, lo);
                stcg64(&g_h1hi[wb][ei], hi);
                stcg64(&g_h1lo[wb][ei], lo);
                if (write_final && t == SEQ - 1) {
                    *(float2*)&out[OUT_MAIN + (size_t)m0*HD + n0]     = make_float2(v0, v1);
                    *(float2*)&out[OUT_MAIN + (size_t)(m0+8)*HD + n0] = make_float2(v2, v3);
                }
            }
            grid_arrive(&g_c1);                          // publish h1(t)
        }
    } else {
        // ---------------- group B: h2 chain (W2 then W1) ----------------
        for (int t = 0; t < SEQ; t++) {
            const int rb = t & 1, wb = rb ^ 1;
            grid_wait(&g_c2, (unsigned)t * NG);          // h2(t-1) visible
#pragma unroll
            for (int ui = 0; ui < 4; ui++)
                D[ui][0] = D[ui][1] = D[ui][2] = D[ui][3] = 0.f;
            // W2: Wh1 x h2(t-1)
            gemm_acc(D, g_h2hi[rb], g_h2lo[rb], sB + 2*SB_ENT, kb0, mbase, gg, tg);
            grid_arrive(&g_c4);                          // W2(t) reads done
            grid_wait(&g_c1, (unsigned)(t + 1) * NG);    // h1(t) visible
            // W1: Wi1 x h1(t)
            gemm_acc(D, g_h1hi[wb], g_h1lo[wb], sB, kb0, mbase, gg, tg);
            grid_arrive(&g_c3);                          // W1(t) reads done
            kredw(D, sred, kw, mbase, lane);
            // peers must be done reading h2 parity wb (their W2 of step t-1)
            grid_wait(&g_c4, (unsigned)t * NG);
            __syncthreads();
            if (wid < 8) {
                kredr(sred, u, lane, r);
                float v0 = tanhf(r[0] + bias0), v1 = tanhf(r[1] + bias1);
                float v2 = tanhf(r[2] + bias0), v3 = tanhf(r[3] + bias1);
                u64 hi, lo; pack_hilo(v0, v1, v2, v3, hi, lo);
                stcg64(&g_h2hi[wb][ei], hi);
                stcg64(&g_h2lo[wb][ei], lo);
                float* ot = out + (size_t)t * BATCH * HD;
                *(float2*)&ot[(size_t)m0*HD + n0]     = make_float2(v0, v1);
                *(float2*)&ot[(size_t)(m0+8)*HD + n0] = make_float2(v2, v3);
                if (write_final && t == SEQ - 1) {
                    float* hf = out + OUT_MAIN + (size_t)BATCH*HD;
                    *(float2*)&hf[(size_t)m0*HD + n0]     = make_float2(v0, v1);
                    *(float2*)&hf[(size_t)(m0+8)*HD + n0] = make_float2(v2, v3);
                }
            }
            grid_arrive(&g_c2);                          // publish h2(t)
        }
    }
}

// ---------------------------------------------------------------------------
extern "C" void kernel_launch(void* const* d_in, const int* in_sizes, int n_in,
                              void* d_out, int out_size) {
    const float* x   = (const float*)d_in[0];
    const float* Wi0 = (const float*)d_in[1];
    const float* bi0 = (const float*)d_in[2];
    const float* Wh0 = (const float*)d_in[3];
    const float* bh0 = (const float*)d_in[4];
    const float* Wi1 = (const float*)d_in[5];
    const float* bi1 = (const float*)d_in[6];
    const float* Wh1 = (const float*)d_in[7];
    const float* bh1 = (const float*)d_in[8];
    float* out = (float*)d_out;

    const int write_final =
        ((size_t)out_size >= OUT_MAIN + (size_t)2 * BATCH * HD) ? 1 : 0;

    cudaFuncSetAttribute(rnn_recurrent_kernel,
                         cudaFuncAttributeMaxDynamicSharedMemorySize, SMEM2_BYTES);
    cudaFuncSetAttribute(rnn_precompute_mma,
                         cudaFuncAttributeMaxDynamicSharedMemorySize, PC_SMEM);

    rnn_reset_kernel<<<256, 256>>>();
    rnn_prepw_kernel<<<(4*GW_ENT + 255)/256, 256>>>(Wh0, Wi1, Wh1, Wi0);
    rnn_xpack_kernel<<<(GX_ENT + 255)/256, 256>>>(x);
    rnn_precompute_mma<<<dim3(16, 256), 256, PC_SMEM>>>(bi0, bh0);
    rnn_recurrent_kernel<<<2*NG, TPB, SMEM2_BYTES>>>(bi1, bh1, out, write_final);
}

// round 10
// speedup vs baseline: 4.0780x; 1.0994x over previous
#include <cuda_runtime.h>
#include <cuda_bf16.h>
#include <math.h>
#include <stdint.h>

#define SEQ   512
#define BATCH 64
#define HD    1024
#define OUT_MAIN ((size_t)SEQ*BATCH*HD)
#define NG    64
#define TPB   512

typedef unsigned long long u64;

#define GH_ENT 16384                    // packed h: [mt4][kb64][g8][c8]
#define GW_ENT 262144                   // packed W: [nfg128][kb64][g8][tg4]
#define GX_ENT 8388608
#define SB_ENT 4096
#define SMEM2_BYTES (4*SB_ENT*8 + 32768)
#define PC_SMEM (8192*8)

__device__ float g_P[33554432];
__device__ u64 g_h1hi[2][GH_ENT], g_h1lo[2][GH_ENT];
__device__ u64 g_h2hi[2][GH_ENT], g_h2lo[2][GH_ENT];
__device__ u64 g_Wp[3][2][GW_ENT];      // [Wh0,Wi1,Wh1][hi,lo]
__device__ u64 g_Wih[GW_ENT], g_Wil[GW_ENT];
__device__ u64 g_xph[GX_ENT], g_xpl[GX_ENT];
__device__ float g_r1[2][NG*1024];      // W1 K-half partials (A -> B)
__device__ unsigned g_c1, g_c2, g_c3, g_c4, g_c5;

__device__ __forceinline__ uint2 ldcg2(const u64* p) {
    uint2 v;
    asm volatile("ld.global.cg.v2.u32 {%0,%1},[%2];" : "=r"(v.x), "=r"(v.y) : "l"(p));
    return v;
}
__device__ __forceinline__ void stcg64(u64* p, u64 v) {
    asm volatile("st.global.cg.u64 [%0],%1;" :: "l"(p), "l"(v));
}
__device__ __forceinline__ float4 ldcg4f(const float* p) {
    float4 v;
    asm volatile("ld.global.cg.v4.f32 {%0,%1,%2,%3},[%4];"
                 : "=f"(v.x), "=f"(v.y), "=f"(v.z), "=f"(v.w) : "l"(p));
    return v;
}
__device__ __forceinline__ void stcg4f(float* p, float4 v) {
    asm volatile("st.global.cg.v4.f32 [%0],{%1,%2,%3,%4};"
                 :: "l"(p), "f"(v.x), "f"(v.y), "f"(v.z), "f"(v.w));
}
__device__ __forceinline__ void mma16816(float d[4], uint2 a01, uint2 a23, uint2 b) {
    asm volatile(
        "mma.sync.aligned.m16n8k16.row.col.f32.bf16.bf16.f32 "
        "{%0,%1,%2,%3},{%4,%5,%6,%7},{%8,%9},{%0,%1,%2,%3};"
        : "+f"(d[0]), "+f"(d[1]), "+f"(d[2]), "+f"(d[3])
        : "r"(a01.x), "r"(a01.y), "r"(a23.x), "r"(a23.y), "r"(b.x), "r"(b.y));
}
__device__ __forceinline__ unsigned short bfu(float x) {
    return __bfloat16_as_ushort(__float2bfloat16(x));
}
__device__ __forceinline__ void pack_hilo(float v0, float v1, float v2, float v3,
                                          u64& hi, u64& lo) {
    unsigned short h0 = bfu(v0), h1 = bfu(v1), h2 = bfu(v2), h3 = bfu(v3);
    unsigned short l0 = bfu(v0 - __bfloat162float(__ushort_as_bfloat16(h0)));
    unsigned short l1 = bfu(v1 - __bfloat162float(__ushort_as_bfloat16(h1)));
    unsigned short l2 = bfu(v2 - __bfloat162float(__ushort_as_bfloat16(h2)));
    unsigned short l3 = bfu(v3 - __bfloat162float(__ushort_as_bfloat16(h3)));
    hi = (u64)h0 | ((u64)h1 << 16) | ((u64)h2 << 32) | ((u64)h3 << 48);
    lo = (u64)l0 | ((u64)l1 << 16) | ((u64)l2 << 32) | ((u64)l3 << 48);
}

// ---------------------------------------------------------------------------
__global__ void rnn_reset_kernel() {
    unsigned idx = blockIdx.x * blockDim.x + threadIdx.x;
    if (idx == 0) { g_c1 = 0u; g_c2 = 0u; g_c3 = 0u; g_c4 = 0u; g_c5 = 0u; }
    if (idx < GH_ENT) {
        g_h1hi[0][idx] = 0ull; g_h1lo[0][idx] = 0ull;
        g_h2hi[0][idx] = 0ull; g_h2lo[0][idx] = 0ull;
    }
}

__global__ __launch_bounds__(256)
void rnn_prepw_kernel(const float* __restrict__ Wh0, const float* __restrict__ Wi1,
                      const float* __restrict__ Wh1, const float* __restrict__ Wi0)
{
    unsigned idx = blockIdx.x * blockDim.x + threadIdx.x;
    if (idx >= 4u * GW_ENT) return;
    const int m = idx / GW_ENT;
    const unsigned e = idx % GW_ENT;
    const int nfg = e >> 11, kb = (e >> 5) & 63, gg = (e >> 2) & 7, tg = e & 3;
    const float* W = (m == 0) ? Wh0 : (m == 1) ? Wi1 : (m == 2) ? Wh1 : Wi0;
    const float* p = W + (size_t)(nfg * 8 + gg) * HD + kb * 16 + tg * 2;
    u64 hi, lo;
    pack_hilo(p[0], p[1], p[8], p[9], hi, lo);
    if (m < 3) { g_Wp[m][0][e] = hi; g_Wp[m][1][e] = lo; }
    else       { g_Wih[e] = hi;      g_Wil[e] = lo; }
}

__global__ __launch_bounds__(256)
void rnn_xpack_kernel(const float* __restrict__ X)
{
    unsigned e = blockIdx.x * blockDim.x + threadIdx.x;
    if (e >= GX_ENT) return;
    const int c = e & 7, gg = (e >> 3) & 7, kb = (e >> 6) & 63, mt = e >> 12;
    const int k = kb * 16 + ((c < 4) ? c * 2 : 8 + (c - 4) * 2);
    const int r0 = mt * 16 + gg;
    const float2 v01 = *(const float2*)&X[(size_t)r0 * HD + k];
    const float2 v23 = *(const float2*)&X[(size_t)(r0 + 8) * HD + k];
    u64 hi, lo;
    pack_hilo(v01.x, v01.y, v23.x, v23.y, hi, lo);
    g_xph[e] = hi; g_xpl[e] = lo;
}

// ---------------------------------------------------------------------------
// precompute via bf16-pair MMA (unchanged, proven)
// ---------------------------------------------------------------------------
__device__ __forceinline__ void pc_stageB(u64* sbase, int ntile, int ch, int tid) {
#pragma unroll
    for (int i = 0; i < 8; i++) {
        const int u = tid + i * 256;
        const int prec = u >> 10, r = u & 1023, nfg = r >> 7, off = (r & 127) * 2;
        const u64* src = (prec ? g_Wil : g_Wih)
                       + ((size_t)(ntile * 8 + nfg) * 64 + ch * 8) * 32 + off;
        unsigned ds = (unsigned)__cvta_generic_to_shared(
            sbase + prec * 2048 + nfg * 256 + off);
        asm volatile("cp.async.cg.shared.global [%0],[%1],16;" :: "r"(ds), "l"(src));
    }
}

__global__ __launch_bounds__(256)
void rnn_precompute_mma(const float* __restrict__ bi0, const float* __restrict__ bh0)
{
    extern __shared__ u64 sB[];
    const int tid = threadIdx.x, wid = tid >> 5, lane = tid & 31;
    const int gg = lane >> 2, tg = lane & 3;
    const int ntile = blockIdx.x;
    const int mt_g = blockIdx.y * 8 + wid;

    float D[8][4];
#pragma unroll
    for (int nf = 0; nf < 8; nf++)
        D[nf][0] = D[nf][1] = D[nf][2] = D[nf][3] = 0.f;

    pc_stageB(sB, ntile, 0, tid);
    asm volatile("cp.async.commit_group;" ::: "memory");

    uint2 Ah01[3], Ah23[3], Al01[3], Al23[3];
#define PCLOADA(s, kb) { \
    const size_t b_ = ((size_t)(mt_g * 64 + (kb)) << 6) + (gg << 3) + tg; \
    Ah01[s] = ldcg2(g_xph + b_); Ah23[s] = ldcg2(g_xph + b_ + 4); \
    Al01[s] = ldcg2(g_xpl + b_); Al23[s] = ldcg2(g_xpl + b_ + 4); }
    PCLOADA(0, 0); PCLOADA(1, 1);

    for (int ch = 0; ch < 8; ch++) {
        if (ch + 1 < 8) {
            pc_stageB(sB + ((ch + 1) & 1) * 4096, ntile, ch + 1, tid);
            asm volatile("cp.async.commit_group;" ::: "memory");
            asm volatile("cp.async.wait_group 1;" ::: "memory");
        } else {
            asm volatile("cp.async.wait_group 0;" ::: "memory");
        }
        __syncthreads();
        const u64* bufp = sB + (ch & 1) * 4096;
#pragma unroll
        for (int kl = 0; kl < 8; kl++) {
            const int kb = ch * 8 + kl;
            if (kb + 2 < 64) PCLOADA((kb + 2) % 3, kb + 2);
            const int c = kb % 3;
            uint2 Bh[8], Bl[8];
#pragma unroll
            for (int nf = 0; nf < 8; nf++) {
                Bh[nf] = *(const uint2*)(bufp + nf * 256 + kl * 32 + lane);
                Bl[nf] = *(const uint2*)(bufp + 2048 + nf * 256 + kl * 32 + lane);
            }
#pragma unroll
            for (int nf = 0; nf < 8; nf++) mma16816(D[nf], Ah01[c], Ah23[c], Bh[nf]);
#pragma unroll
            for (int nf = 0; nf < 8; nf++) mma16816(D[nf], Ah01[c], Ah23[c], Bl[nf]);
#pragma unroll
            for (int nf = 0; nf < 8; nf++) mma16816(D[nf], Al01[c], Al23[c], Bh[nf]);
        }
        __syncthreads();
    }
#undef PCLOADA

    const int r0 = mt_g * 16 + gg;
#pragma unroll
    for (int nf = 0; nf < 8; nf++) {
        const int n0 = ntile * 64 + nf * 8 + tg * 2;
        const float b0 = bi0[n0] + bh0[n0], b1 = bi0[n0 + 1] + bh0[n0 + 1];
        *(float2*)&g_P[(size_t)r0 * HD + n0]       = make_float2(D[nf][0] + b0, D[nf][1] + b1);
        *(float2*)&g_P[(size_t)(r0 + 8) * HD + n0] = make_float2(D[nf][2] + b0, D[nf][3] + b1);
    }
}

// ---------------------------------------------------------------------------
__device__ __forceinline__ void grid_arrive(unsigned* c) {
    __threadfence();
    __syncthreads();
    if (threadIdx.x == 0) atomicAdd(c, 1u);
}
__device__ __forceinline__ void grid_wait(unsigned* c, unsigned target) {
    if (threadIdx.x == 0) {
        while (*((volatile unsigned*)c) < target) __nanosleep(16);
        __threadfence();
    }
    __syncthreads();
}

// warp GEMM slice over NJ kb-iterations starting at kb0 (A prefetch depth 2,
// B register double-buffer, term-major order).
template<int NJ>
__device__ __forceinline__ void gemm_acc(float (&D)[4][4],
    const u64* __restrict__ ghHi, const u64* __restrict__ ghLo,
    const u64* __restrict__ sBhi, int kb0, int mbase, int gg, int tg)
{
    uint2 Ah01[3][2], Ah23[3][2], Al01[3][2], Al23[3][2];
#pragma unroll
    for (int p = 0; p < 2; p++)
#pragma unroll
        for (int mi = 0; mi < 2; mi++) {
            const size_t b = ((size_t)((mbase+mi)*64 + kb0 + p) << 6) + (gg<<3) + tg;
            Ah01[p][mi] = ldcg2(ghHi+b);  Ah23[p][mi] = ldcg2(ghHi+b+4);
            Al01[p][mi] = ldcg2(ghLo+b);  Al23[p][mi] = ldcg2(ghLo+b+4);
        }
    uint2 Bh0[2], Bh1[2], Bl0[2], Bl1[2];
    {
        const int bi = (kb0 << 5) + (gg << 2) + tg;
        Bh0[0] = *(const uint2*)(sBhi + bi);
        Bh1[0] = *(const uint2*)(sBhi + 2048 + bi);
        Bl0[0] = *(const uint2*)(sBhi + SB_ENT + bi);
        Bl1[0] = *(const uint2*)(sBhi + SB_ENT + 2048 + bi);
    }
#pragma unroll
    for (int j = 0; j < NJ; j++) {
        const int cb = j & 1, nb = cb ^ 1;
        if (j < NJ - 1) {
            const int bi = ((kb0 + j + 1) << 5) + (gg << 2) + tg;
            Bh0[nb] = *(const uint2*)(sBhi + bi);
            Bh1[nb] = *(const uint2*)(sBhi + 2048 + bi);
            Bl0[nb] = *(const uint2*)(sBhi + SB_ENT + bi);
            Bl1[nb] = *(const uint2*)(sBhi + SB_ENT + 2048 + bi);
        }
        if (j + 2 < NJ) {
            const int s = (j + 2) % 3;
#pragma unroll
            for (int mi = 0; mi < 2; mi++) {
                const size_t b = ((size_t)((mbase+mi)*64 + kb0 + j + 2) << 6) + (gg<<3) + tg;
                Ah01[s][mi] = ldcg2(ghHi+b);  Ah23[s][mi] = ldcg2(ghHi+b+4);
                Al01[s][mi] = ldcg2(ghLo+b);  Al23[s][mi] = ldcg2(ghLo+b+4);
            }
        }
        const int c = j % 3;
        mma16816(D[0], Ah01[c][0], Ah23[c][0], Bh0[cb]);
        mma16816(D[1], Ah01[c][0], Ah23[c][0], Bh1[cb]);
        mma16816(D[2], Ah01[c][1], Ah23[c][1], Bh0[cb]);
        mma16816(D[3], Ah01[c][1], Ah23[c][1], Bh1[cb]);
        mma16816(D[0], Ah01[c][0], Ah23[c][0], Bl0[cb]);
        mma16816(D[1], Ah01[c][0], Ah23[c][0], Bl1[cb]);
        mma16816(D[2], Ah01[c][1], Ah23[c][1], Bl0[cb]);
        mma16816(D[3], Ah01[c][1], Ah23[c][1], Bl1[cb]);
        mma16816(D[0], Al01[c][0], Al23[c][0], Bh0[cb]);
        mma16816(D[1], Al01[c][0], Al23[c][0], Bh1[cb]);
        mma16816(D[2], Al01[c][1], Al23[c][1], Bh0[cb]);
        mma16816(D[3], Al01[c][1], Al23[c][1], Bh1[cb]);
    }
}

__device__ __forceinline__ void kredw(const float (&D)[4][4], float* sred,
                                      int kw, int mbase, int lane)
{
    const int sw = lane & 7;
#pragma unroll
    for (int ui = 0; ui < 4; ui++) {
        const int u = (mbase + (ui >> 1)) * 2 + (ui & 1);
        float4* p = (float4*)&sred[((((u*32+lane) << 3) + (kw ^ sw)) << 2)];
        *p = make_float4(D[ui][0], D[ui][1], D[ui][2], D[ui][3]);
    }
}
__device__ __forceinline__ void kredr(const float* sred, int u, int lane, float r[4]) {
    const int sw = lane & 7;
    r[0] = r[1] = r[2] = r[3] = 0.f;
#pragma unroll
    for (int w = 0; w < 8; w++) {
        float4 v = *(const float4*)&sred[((((u*32+lane) << 3) + (w ^ sw)) << 2)];
        r[0] += v.x; r[1] += v.y; r[2] += v.z; r[3] += v.w;
    }
}

// ---------------------------------------------------------------------------
// pipeline-parallel recurrent: A = W0 + W1-K-half; B = W2 + W1-K-half.
// counters: c1 h1 published | c2 h2 published | c3 B done W1 reads |
//           c4 B done W2 reads | c5 A's W1 partial published
// ---------------------------------------------------------------------------
__global__ __launch_bounds__(TPB)
void rnn_recurrent_kernel(const float* __restrict__ bi1,
                          const float* __restrict__ bh1,
                          float* __restrict__ out,
                          int write_final)
{
    extern __shared__ u64 smem_u64[];
    u64*   sB   = smem_u64;
    float* sred = (float*)(smem_u64 + 4*SB_ENT);

    const int tid  = threadIdx.x;
    const int wid  = tid >> 5;
    const int lane = tid & 31;
    const int gg   = lane >> 2;
    const int tg   = lane & 3;
    const int grpB = (blockIdx.x >= NG);
    const int cta  = grpB ? (blockIdx.x - NG) : blockIdx.x;
    const int kw   = wid >> 1;
    const int mbase = (wid & 1) * 2;

    // A: slots 0,1 = Wh0 hi/lo; slots 2,3 = Wi1 hi/lo.
    // B: slots 0,1 = Wi1 hi/lo; slots 2,3 = Wh1 hi/lo.
#pragma unroll
    for (int mp = 0; mp < 4; mp++) {
        const int mat = grpB ? ((mp >> 1) + 1) : (mp >> 1);
        const u64* src = g_Wp[mat][mp & 1] + (size_t)cta * SB_ENT;
        u64* dst = sB + mp * SB_ENT;
        for (int i = tid * 2; i < SB_ENT; i += TPB * 2)
            *(uint4*)(dst + i) = *(const uint4*)(src + i);
    }

    const int u  = wid & 7;
    const int mt = u >> 1, nf = u & 1;
    const int m0 = mt * 16 + gg;
    const int n0 = cta * 16 + nf * 8 + tg * 2;
    const unsigned ei = (unsigned)((mt * 64 + cta) << 6) + (gg << 3) + (nf * 4 + tg);
    const unsigned pi = ((unsigned)cta << 10) + ((unsigned)u << 7) + ((unsigned)lane << 2);
    const float bias0 = bi1[n0] + bh1[n0];
    const float bias1 = bi1[n0+1] + bh1[n0+1];
    __syncthreads();

    float D[4][4], r[4];

    if (!grpB) {
        // ------------- group A -------------
        for (int t = 0; t < SEQ; t++) {
            const int rb = t & 1, wb = rb ^ 1;
#pragma unroll
            for (int ui = 0; ui < 4; ui++)
                D[ui][0] = D[ui][1] = D[ui][2] = D[ui][3] = 0.f;
            // W0: Wh0 x h1(t-1), full K
            gemm_acc<8>(D, g_h1hi[rb], g_h1lo[rb], sB, kw * 8, mbase, gg, tg);
            kredw(D, sred, kw, mbase, lane);
            grid_wait(&g_c3, (t >= 2) ? (unsigned)(t - 1) * NG : 0u);
            __syncthreads();
            if (wid < 8) {
                kredr(sred, u, lane, r);
                const float* Pt = g_P + (size_t)t * BATCH * HD;
                const float2 p0 = __ldg((const float2*)(Pt + (size_t)m0 * HD + n0));
                const float2 p1 = __ldg((const float2*)(Pt + (size_t)(m0+8) * HD + n0));
                float v0 = tanhf(r[0] + p0.x), v1 = tanhf(r[1] + p0.y);
                float v2 = tanhf(r[2] + p1.x), v3 = tanhf(r[3] + p1.y);
                u64 hi, lo; pack_hilo(v0, v1, v2, v3, hi, lo);
                stcg64(&g_h1hi[wb][ei], hi);
                stcg64(&g_h1lo[wb][ei], lo);
                if (write_final && t == SEQ - 1) {
                    *(float2*)&out[OUT_MAIN + (size_t)m0*HD + n0]     = make_float2(v0, v1);
                    *(float2*)&out[OUT_MAIN + (size_t)(m0+8)*HD + n0] = make_float2(v2, v3);
                }
            }
            grid_arrive(&g_c1);                      // publish h1(t)

            // W1 first K-half: needs h1(t) from ALL A CTAs
            grid_wait(&g_c1, (unsigned)(t + 1) * NG);
#pragma unroll
            for (int ui = 0; ui < 4; ui++)
                D[ui][0] = D[ui][1] = D[ui][2] = D[ui][3] = 0.f;
            gemm_acc<4>(D, g_h1hi[wb], g_h1lo[wb], sB + 2*SB_ENT, kw * 4, mbase, gg, tg);
            kredw(D, sred, kw, mbase, lane);
            // g_r1[wb] anti-dep: B's step-(t-2) epilogue read done
            grid_wait(&g_c2, (t >= 1) ? (unsigned)(t - 1) * NG : 0u);
            __syncthreads();
            if (wid < 8) {
                kredr(sred, u, lane, r);
                stcg4f(&g_r1[wb][pi], make_float4(r[0], r[1], r[2], r[3]));
            }
            grid_arrive(&g_c5);                      // publish W1 partial(t)
        }
    } else {
        // ------------- group B -------------
        for (int t = 0; t < SEQ; t++) {
            const int rb = t & 1, wb = rb ^ 1;
            grid_wait(&g_c2, (unsigned)t * NG);      // h2(t-1) visible
#pragma unroll
            for (int ui = 0; ui < 4; ui++)
                D[ui][0] = D[ui][1] = D[ui][2] = D[ui][3] = 0.f;
            // W2: Wh1 x h2(t-1), full K
            gemm_acc<8>(D, g_h2hi[rb], g_h2lo[rb], sB + 2*SB_ENT, kw * 8, mbase, gg, tg);
            grid_arrive(&g_c4);                      // W2(t) reads done
            grid_wait(&g_c1, (unsigned)(t + 1) * NG);// h1(t) visible
            // W1 second K-half: Wi1 x h1(t), kb 32..63
            gemm_acc<4>(D, g_h1hi[wb], g_h1lo[wb], sB, 32 + kw * 4, mbase, gg, tg);
            grid_arrive(&g_c3);                      // W1(t) reads done
            kredw(D, sred, kw, mbase, lane);
            grid_wait(&g_c4, (unsigned)t * NG);      // peers done W2(t-1) reads
            grid_wait(&g_c5, (unsigned)(t + 1) * NG);// A's partial(t) ready
            __syncthreads();
            if (wid < 8) {
                kredr(sred, u, lane, r);
                const float4 pa = ldcg4f(&g_r1[wb][pi]);
                float v0 = tanhf(r[0] + pa.x + bias0), v1 = tanhf(r[1] + pa.y + bias1);
                float v2 = tanhf(r[2] + pa.z + bias0), v3 = tanhf(r[3] + pa.w + bias1);
                u64 hi, lo; pack_hilo(v0, v1, v2, v3, hi, lo);
                stcg64(&g_h2hi[wb][ei], hi);
                stcg64(&g_h2lo[wb][ei], lo);
                float* ot = out + (size_t)t * BATCH * HD;
                *(float2*)&ot[(size_t)m0*HD + n0]     = make_float2(v0, v1);
                *(float2*)&ot[(size_t)(m0+8)*HD + n0] = make_float2(v2, v3);
                if (write_final && t == SEQ - 1) {
                    float* hf = out + OUT_MAIN + (size_t)BATCH*HD;
                    *(float2*)&hf[(size_t)m0*HD + n0]     = make_float2(v0, v1);
                    *(float2*)&hf[(size_t)(m0+8)*HD + n0] = make_float2(v2, v3);
                }
            }
            grid_arrive(&g_c2);                      // publish h2(t)
        }
    }
}

// ---------------------------------------------------------------------------
extern "C" void kernel_launch(void* const* d_in, const int* in_sizes, int n_in,
                              void* d_out, int out_size) {
    const float* x   = (const float*)d_in[0];
    const float* Wi0 = (const float*)d_in[1];
    const float* bi0 = (const float*)d_in[2];
    const float* Wh0 = (const float*)d_in[3];
    const float* bh0 = (const float*)d_in[4];
    const float* Wi1 = (const float*)d_in[5];
    const float* bi1 = (const float*)d_in[6];
    const float* Wh1 = (const float*)d_in[7];
    const float* bh1 = (const float*)d_in[8];
    float* out = (float*)d_out;

    const int write_final =
        ((size_t)out_size >= OUT_MAIN + (size_t)2 * BATCH * HD) ? 1 : 0;

    cudaFuncSetAttribute(rnn_recurrent_kernel,
                         cudaFuncAttributeMaxDynamicSharedMemorySize, SMEM2_BYTES);
    cudaFuncSetAttribute(rnn_precompute_mma,
                         cudaFuncAttributeMaxDynamicSharedMemorySize, PC_SMEM);

    rnn_reset_kernel<<<256, 256>>>();
    rnn_prepw_kernel<<<(4*GW_ENT + 255)/256, 256>>>(Wh0, Wi1, Wh1, Wi0);
    rnn_xpack_kernel<<<(GX_ENT + 255)/256, 256>>>(x);
    rnn_precompute_mma<<<dim3(16, 256), 256, PC_SMEM>>>(bi0, bh0);
    rnn_recurrent_kernel<<<2*NG, TPB, SMEM2_BYTES>>>(bi1, bh1, out, write_final);
}

// round 12
// speedup vs baseline: 4.7701x; 1.1697x over previous
#include <cuda_runtime.h>
#include <cuda_bf16.h>
#include <math.h>
#include <stdint.h>

#define SEQ   512
#define BATCH 64
#define HD    1024
#define OUT_MAIN ((size_t)SEQ*BATCH*HD)
#define NG    64
#define TPB   512

typedef unsigned long long u64;

#define GH_ENT 16384                    // packed h: [mt4][kb64][g8][c8]
#define GW_ENT 262144                   // packed W: [nfg128][kb64][g8][tg4]
#define GX_ENT 8388608
#define SB_ENT 4096
#define SMEM2_BYTES (4*SB_ENT*8 + 32768)
#define PC_SMEM (8192*8)

__device__ float g_P[33554432];
__device__ u64 g_h1hi[3][GH_ENT], g_h1lo[3][GH_ENT];   // triple-buffered
__device__ u64 g_h2hi[3][GH_ENT], g_h2lo[3][GH_ENT];
__device__ u64 g_Wp[3][2][GW_ENT];      // [Wh0,Wi1,Wh1][hi,lo]
__device__ u64 g_Wih[GW_ENT], g_Wil[GW_ENT];
__device__ u64 g_xph[GX_ENT], g_xpl[GX_ENT];
__device__ float g_r1[3][NG*1024];      // W1 K-half partials (A -> B)
__device__ unsigned g_c1, g_c2, g_c5;

__device__ __forceinline__ uint2 ldcg2(const u64* p) {
    uint2 v;
    asm volatile("ld.global.cg.v2.u32 {%0,%1},[%2];" : "=r"(v.x), "=r"(v.y) : "l"(p));
    return v;
}
__device__ __forceinline__ void stcg64(u64* p, u64 v) {
    asm volatile("st.global.cg.u64 [%0],%1;" :: "l"(p), "l"(v));
}
__device__ __forceinline__ float4 ldcg4f(const float* p) {
    float4 v;
    asm volatile("ld.global.cg.v4.f32 {%0,%1,%2,%3},[%4];"
                 : "=f"(v.x), "=f"(v.y), "=f"(v.z), "=f"(v.w) : "l"(p));
    return v;
}
__device__ __forceinline__ void stcg4f(float* p, float4 v) {
    asm volatile("st.global.cg.v4.f32 [%0],{%1,%2,%3,%4};"
                 :: "l"(p), "f"(v.x), "f"(v.y), "f"(v.z), "f"(v.w));
}
__device__ __forceinline__ void mma16816(float d[4], uint2 a01, uint2 a23, uint2 b) {
    asm volatile(
        "mma.sync.aligned.m16n8k16.row.col.f32.bf16.bf16.f32 "
        "{%0,%1,%2,%3},{%4,%5,%6,%7},{%8,%9},{%0,%1,%2,%3};"
        : "+f"(d[0]), "+f"(d[1]), "+f"(d[2]), "+f"(d[3])
        : "r"(a01.x), "r"(a01.y), "r"(a23.x), "r"(a23.y), "r"(b.x), "r"(b.y));
}
__device__ __forceinline__ unsigned short bfu(float x) {
    return __bfloat16_as_ushort(__float2bfloat16(x));
}
__device__ __forceinline__ void pack_hilo(float v0, float v1, float v2, float v3,
                                          u64& hi, u64& lo) {
    unsigned short h0 = bfu(v0), h1 = bfu(v1), h2 = bfu(v2), h3 = bfu(v3);
    unsigned short l0 = bfu(v0 - __bfloat162float(__ushort_as_bfloat16(h0)));
    unsigned short l1 = bfu(v1 - __bfloat162float(__ushort_as_bfloat16(h1)));
    unsigned short l2 = bfu(v2 - __bfloat162float(__ushort_as_bfloat16(h2)));
    unsigned short l3 = bfu(v3 - __bfloat162float(__ushort_as_bfloat16(h3)));
    hi = (u64)h0 | ((u64)h1 << 16) | ((u64)h2 << 32) | ((u64)h3 << 48);
    lo = (u64)l0 | ((u64)l1 << 16) | ((u64)l2 << 32) | ((u64)l3 << 48);
}

// ---------------------------------------------------------------------------
__global__ void rnn_reset_kernel() {
    unsigned idx = blockIdx.x * blockDim.x + threadIdx.x;
    if (idx == 0) { g_c1 = 0u; g_c2 = 0u; g_c5 = 0u; }
    if (idx < GH_ENT) {                 // t=0 reads parity (0-1)%3 = 2
        g_h1hi[2][idx] = 0ull; g_h1lo[2][idx] = 0ull;
        g_h2hi[2][idx] = 0ull; g_h2lo[2][idx] = 0ull;
    }
}

__global__ __launch_bounds__(256)
void rnn_prepw_kernel(const float* __restrict__ Wh0, const float* __restrict__ Wi1,
                      const float* __restrict__ Wh1, const float* __restrict__ Wi0)
{
    unsigned idx = blockIdx.x * blockDim.x + threadIdx.x;
    if (idx >= 4u * GW_ENT) return;
    const int m = idx / GW_ENT;
    const unsigned e = idx % GW_ENT;
    const int nfg = e >> 11, kb = (e >> 5) & 63, gg = (e >> 2) & 7, tg = e & 3;
    const float* W = (m == 0) ? Wh0 : (m == 1) ? Wi1 : (m == 2) ? Wh1 : Wi0;
    const float* p = W + (size_t)(nfg * 8 + gg) * HD + kb * 16 + tg * 2;
    u64 hi, lo;
    pack_hilo(p[0], p[1], p[8], p[9], hi, lo);
    if (m < 3) { g_Wp[m][0][e] = hi; g_Wp[m][1][e] = lo; }
    else       { g_Wih[e] = hi;      g_Wil[e] = lo; }
}

__global__ __launch_bounds__(256)
void rnn_xpack_kernel(const float* __restrict__ X)
{
    unsigned e = blockIdx.x * blockDim.x + threadIdx.x;
    if (e >= GX_ENT) return;
    const int c = e & 7, gg = (e >> 3) & 7, kb = (e >> 6) & 63, mt = e >> 12;
    const int k = kb * 16 + ((c < 4) ? c * 2 : 8 + (c - 4) * 2);
    const int r0 = mt * 16 + gg;
    const float2 v01 = *(const float2*)&X[(size_t)r0 * HD + k];
    const float2 v23 = *(const float2*)&X[(size_t)(r0 + 8) * HD + k];
    u64 hi, lo;
    pack_hilo(v01.x, v01.y, v23.x, v23.y, hi, lo);
    g_xph[e] = hi; g_xpl[e] = lo;
}

// ---------------------------------------------------------------------------
// precompute via bf16-pair MMA (unchanged, proven)
// ---------------------------------------------------------------------------
__device__ __forceinline__ void pc_stageB(u64* sbase, int ntile, int ch, int tid) {
#pragma unroll
    for (int i = 0; i < 8; i++) {
        const int u = tid + i * 256;
        const int prec = u >> 10, r = u & 1023, nfg = r >> 7, off = (r & 127) * 2;
        const u64* src = (prec ? g_Wil : g_Wih)
                       + ((size_t)(ntile * 8 + nfg) * 64 + ch * 8) * 32 + off;
        unsigned ds = (unsigned)__cvta_generic_to_shared(
            sbase + prec * 2048 + nfg * 256 + off);
        asm volatile("cp.async.cg.shared.global [%0],[%1],16;" :: "r"(ds), "l"(src));
    }
}

__global__ __launch_bounds__(256)
void rnn_precompute_mma(const float* __restrict__ bi0, const float* __restrict__ bh0)
{
    extern __shared__ u64 sB[];
    const int tid = threadIdx.x, wid = tid >> 5, lane = tid & 31;
    const int gg = lane >> 2, tg = lane & 3;
    const int ntile = blockIdx.x;
    const int mt_g = blockIdx.y * 8 + wid;

    float D[8][4];
#pragma unroll
    for (int nf = 0; nf < 8; nf++)
        D[nf][0] = D[nf][1] = D[nf][2] = D[nf][3] = 0.f;

    pc_stageB(sB, ntile, 0, tid);
    asm volatile("cp.async.commit_group;" ::: "memory");

    uint2 Ah01[3], Ah23[3], Al01[3], Al23[3];
#define PCLOADA(s, kb) { \
    const size_t b_ = ((size_t)(mt_g * 64 + (kb)) << 6) + (gg << 3) + tg; \
    Ah01[s] = ldcg2(g_xph + b_); Ah23[s] = ldcg2(g_xph + b_ + 4); \
    Al01[s] = ldcg2(g_xpl + b_); Al23[s] = ldcg2(g_xpl + b_ + 4); }
    PCLOADA(0, 0); PCLOADA(1, 1);

    for (int ch = 0; ch < 8; ch++) {
        if (ch + 1 < 8) {
            pc_stageB(sB + ((ch + 1) & 1) * 4096, ntile, ch + 1, tid);
            asm volatile("cp.async.commit_group;" ::: "memory");
            asm volatile("cp.async.wait_group 1;" ::: "memory");
        } else {
            asm volatile("cp.async.wait_group 0;" ::: "memory");
        }
        __syncthreads();
        const u64* bufp = sB + (ch & 1) * 4096;
#pragma unroll
        for (int kl = 0; kl < 8; kl++) {
            const int kb = ch * 8 + kl;
            if (kb + 2 < 64) PCLOADA((kb + 2) % 3, kb + 2);
            const int c = kb % 3;
            uint2 Bh[8], Bl[8];
#pragma unroll
            for (int nf = 0; nf < 8; nf++) {
                Bh[nf] = *(const uint2*)(bufp + nf * 256 + kl * 32 + lane);
                Bl[nf] = *(const uint2*)(bufp + 2048 + nf * 256 + kl * 32 + lane);
            }
#pragma unroll
            for (int nf = 0; nf < 8; nf++) mma16816(D[nf], Ah01[c], Ah23[c], Bh[nf]);
#pragma unroll
            for (int nf = 0; nf < 8; nf++) mma16816(D[nf], Ah01[c], Ah23[c], Bl[nf]);
#pragma unroll
            for (int nf = 0; nf < 8; nf++) mma16816(D[nf], Al01[c], Al23[c], Bh[nf]);
        }
        __syncthreads();
    }
#undef PCLOADA

    const int r0 = mt_g * 16 + gg;
#pragma unroll
    for (int nf = 0; nf < 8; nf++) {
        const int n0 = ntile * 64 + nf * 8 + tg * 2;
        const float b0 = bi0[n0] + bh0[n0], b1 = bi0[n0 + 1] + bh0[n0 + 1];
        *(float2*)&g_P[(size_t)r0 * HD + n0]       = make_float2(D[nf][0] + b0, D[nf][1] + b1);
        *(float2*)&g_P[(size_t)(r0 + 8) * HD + n0] = make_float2(D[nf][2] + b0, D[nf][3] + b1);
    }
}

// ---------------------------------------------------------------------------
// grid sync (R10-proven primitives)
// ---------------------------------------------------------------------------
__device__ __forceinline__ void grid_arrive(unsigned* c) {
    __threadfence();
    __syncthreads();
    if (threadIdx.x == 0) atomicAdd(c, 1u);
}
__device__ __forceinline__ void grid_wait(unsigned* c, unsigned target) {
    if (threadIdx.x == 0) {
        while (*((volatile unsigned*)c) < target) __nanosleep(16);
        __threadfence();
    }
    __syncthreads();
}

// warp GEMM slice over NJ kb-iterations starting at kb0
template<int NJ>
__device__ __forceinline__ void gemm_acc(float (&D)[4][4],
    const u64* __restrict__ ghHi, const u64* __restrict__ ghLo,
    const u64* __restrict__ sBhi, int kb0, int mbase, int gg, int tg)
{
    uint2 Ah01[3][2], Ah23[3][2], Al01[3][2], Al23[3][2];
#pragma unroll
    for (int p = 0; p < 2; p++)
#pragma unroll
        for (int mi = 0; mi < 2; mi++) {
            const size_t b = ((size_t)((mbase+mi)*64 + kb0 + p) << 6) + (gg<<3) + tg;
            Ah01[p][mi] = ldcg2(ghHi+b);  Ah23[p][mi] = ldcg2(ghHi+b+4);
            Al01[p][mi] = ldcg2(ghLo+b);  Al23[p][mi] = ldcg2(ghLo+b+4);
        }
    uint2 Bh0[2], Bh1[2], Bl0[2], Bl1[2];
    {
        const int bi = (kb0 << 5) + (gg << 2) + tg;
        Bh0[0] = *(const uint2*)(sBhi + bi);
        Bh1[0] = *(const uint2*)(sBhi + 2048 + bi);
        Bl0[0] = *(const uint2*)(sBhi + SB_ENT + bi);
        Bl1[0] = *(const uint2*)(sBhi + SB_ENT + 2048 + bi);
    }
#pragma unroll
    for (int j = 0; j < NJ; j++) {
        const int cb = j & 1, nb = cb ^ 1;
        if (j < NJ - 1) {
            const int bi = ((kb0 + j + 1) << 5) + (gg << 2) + tg;
            Bh0[nb] = *(const uint2*)(sBhi + bi);
            Bh1[nb] = *(const uint2*)(sBhi + 2048 + bi);
            Bl0[nb] = *(const uint2*)(sBhi + SB_ENT + bi);
            Bl1[nb] = *(const uint2*)(sBhi + SB_ENT + 2048 + bi);
        }
        if (j + 2 < NJ) {
            const int s = (j + 2) % 3;
#pragma unroll
            for (int mi = 0; mi < 2; mi++) {
                const size_t b = ((size_t)((mbase+mi)*64 + kb0 + j + 2) << 6) + (gg<<3) + tg;
                Ah01[s][mi] = ldcg2(ghHi+b);  Ah23[s][mi] = ldcg2(ghHi+b+4);
                Al01[s][mi] = ldcg2(ghLo+b);  Al23[s][mi] = ldcg2(ghLo+b+4);
            }
        }
        const int c = j % 3;
        mma16816(D[0], Ah01[c][0], Ah23[c][0], Bh0[cb]);
        mma16816(D[1], Ah01[c][0], Ah23[c][0], Bh1[cb]);
        mma16816(D[2], Ah01[c][1], Ah23[c][1], Bh0[cb]);
        mma16816(D[3], Ah01[c][1], Ah23[c][1], Bh1[cb]);
        mma16816(D[0], Ah01[c][0], Ah23[c][0], Bl0[cb]);
        mma16816(D[1], Ah01[c][0], Ah23[c][0], Bl1[cb]);
        mma16816(D[2], Ah01[c][1], Ah23[c][1], Bl0[cb]);
        mma16816(D[3], Ah01[c][1], Ah23[c][1], Bl1[cb]);
        mma16816(D[0], Al01[c][0], Al23[c][0], Bh0[cb]);
        mma16816(D[1], Al01[c][0], Al23[c][0], Bh1[cb]);
        mma16816(D[2], Al01[c][1], Al23[c][1], Bh0[cb]);
        mma16816(D[3], Al01[c][1], Al23[c][1], Bh1[cb]);
    }
}

__device__ __forceinline__ void kredw(const float (&D)[4][4], float* sred,
                                      int kw, int mbase, int lane)
{
    const int sw = lane & 7;
#pragma unroll
    for (int ui = 0; ui < 4; ui++) {
        const int u = (mbase + (ui >> 1)) * 2 + (ui & 1);
        float4* p = (float4*)&sred[((((u*32+lane) << 3) + (kw ^ sw)) << 2)];
        *p = make_float4(D[ui][0], D[ui][1], D[ui][2], D[ui][3]);
    }
}
__device__ __forceinline__ void kredr(const float* sred, int u, int lane, float r[4]) {
    const int sw = lane & 7;
    r[0] = r[1] = r[2] = r[3] = 0.f;
#pragma unroll
    for (int w = 0; w < 8; w++) {
        float4 v = *(const float4*)&sred[((((u*32+lane) << 3) + (w ^ sw)) << 2)];
        r[0] += v.x; r[1] += v.y; r[2] += v.z; r[3] += v.w;
    }
}

// ---------------------------------------------------------------------------
// pipeline-parallel recurrent, triple-buffered state.
// counters: c1 h1 published | c2 h2 published | c5 A's W1 partial published
// ---------------------------------------------------------------------------
__global__ __launch_bounds__(TPB)
void rnn_recurrent_kernel(const float* __restrict__ bi1,
                          const float* __restrict__ bh1,
                          float* __restrict__ out,
                          int write_final)
{
    extern __shared__ u64 smem_u64[];
    u64*   sB   = smem_u64;
    float* sred = (float*)(smem_u64 + 4*SB_ENT);

    const int tid  = threadIdx.x;
    const int wid  = tid >> 5;
    const int lane = tid & 31;
    const int gg   = lane >> 2;
    const int tg   = lane & 3;
    const int grpB = (blockIdx.x >= NG);
    const int cta  = grpB ? (blockIdx.x - NG) : blockIdx.x;
    const int kw   = wid >> 1;
    const int mbase = (wid & 1) * 2;

    // A: slots 0,1 = Wh0 hi/lo; slots 2,3 = Wi1 hi/lo.
    // B: slots 0,1 = Wi1 hi/lo; slots 2,3 = Wh1 hi/lo.
#pragma unroll
    for (int mp = 0; mp < 4; mp++) {
        const int mat = grpB ? ((mp >> 1) + 1) : (mp >> 1);
        const u64* src = g_Wp[mat][mp & 1] + (size_t)cta * SB_ENT;
        u64* dst = sB + mp * SB_ENT;
        for (int i = tid * 2; i < SB_ENT; i += TPB * 2)
            *(uint4*)(dst + i) = *(const uint4*)(src + i);
    }

    const int u  = wid & 7;
    const int mt = u >> 1, nf = u & 1;
    const int m0 = mt * 16 + gg;
    const int n0 = cta * 16 + nf * 8 + tg * 2;
    const unsigned ei = (unsigned)((mt * 64 + cta) << 6) + (gg << 3) + (nf * 4 + tg);
    const unsigned pi = ((unsigned)cta << 10) + ((unsigned)u << 7) + ((unsigned)lane << 2);
    const float bias0 = bi1[n0] + bh1[n0];
    const float bias1 = bi1[n0+1] + bh1[n0+1];
    __syncthreads();

    float D[4][4], r[4];

    if (!grpB) {
        // ------------- group A: W0 (full K) + W1 first K-half -------------
        for (int t = 0; t < SEQ; t++) {
            const int rp = (t + 2) % 3, wp = t % 3;
            // prefetch P(t) early (off the epilogue critical path)
            float2 pf0, pf1;
            if (wid < 8) {
                const float* Pt = g_P + (size_t)t * BATCH * HD;
                pf0 = __ldg((const float2*)(Pt + (size_t)m0 * HD + n0));
                pf1 = __ldg((const float2*)(Pt + (size_t)(m0+8) * HD + n0));
            }
#pragma unroll
            for (int ui = 0; ui < 4; ui++)
                D[ui][0] = D[ui][1] = D[ui][2] = D[ui][3] = 0.f;
            gemm_acc<8>(D, g_h1hi[rp], g_h1lo[rp], sB, kw * 8, mbase, gg, tg);
            kredw(D, sred, kw, mbase, lane);
            // slack wait: B's epi(t-3) done -> h1[wp], g_r1[wp] reusable
            grid_wait(&g_c2, (t >= 2) ? (unsigned)(t - 2) * NG : 0u);
            __syncthreads();
            if (wid < 8) {
                kredr(sred, u, lane, r);
                float v0 = tanhf(r[0] + pf0.x), v1 = tanhf(r[1] + pf0.y);
                float v2 = tanhf(r[2] + pf1.x), v3 = tanhf(r[3] + pf1.y);
                u64 hi, lo; pack_hilo(v0, v1, v2, v3, hi, lo);
                stcg64(&g_h1hi[wp][ei], hi);
                stcg64(&g_h1lo[wp][ei], lo);
                if (write_final && t == SEQ - 1) {
                    *(float2*)&out[OUT_MAIN + (size_t)m0*HD + n0]     = make_float2(v0, v1);
                    *(float2*)&out[OUT_MAIN + (size_t)(m0+8)*HD + n0] = make_float2(v2, v3);
                }
            }
            grid_arrive(&g_c1);                      // publish h1(t)
            grid_wait(&g_c1, (unsigned)(t + 1) * NG);
#pragma unroll
            for (int ui = 0; ui < 4; ui++)
                D[ui][0] = D[ui][1] = D[ui][2] = D[ui][3] = 0.f;
            gemm_acc<4>(D, g_h1hi[wp], g_h1lo[wp], sB + 2*SB_ENT, kw * 4, mbase, gg, tg);
            kredw(D, sred, kw, mbase, lane);
            __syncthreads();
            if (wid < 8) {
                kredr(sred, u, lane, r);
                stcg4f(&g_r1[wp][pi], make_float4(r[0], r[1], r[2], r[3]));
            }
            grid_arrive(&g_c5);                      // publish W1 partial(t)
        }
    } else {
        // ------------- group B: W2 (full K) + W1 second K-half -------------
        for (int t = 0; t < SEQ; t++) {
            const int rp = (t + 2) % 3, wp = t % 3;
            grid_wait(&g_c2, (unsigned)t * NG);      // all B epi(t-1) done
#pragma unroll
            for (int ui = 0; ui < 4; ui++)
                D[ui][0] = D[ui][1] = D[ui][2] = D[ui][3] = 0.f;
            gemm_acc<8>(D, g_h2hi[rp], g_h2lo[rp], sB + 2*SB_ENT, kw * 8, mbase, gg, tg);
            grid_wait(&g_c1, (unsigned)(t + 1) * NG);// h1(t) visible
            gemm_acc<4>(D, g_h1hi[wp], g_h1lo[wp], sB, 32 + kw * 4, mbase, gg, tg);
            kredw(D, sred, kw, mbase, lane);
            grid_wait(&g_c5, (unsigned)(t + 1) * NG);// A's partial(t) ready
            __syncthreads();
            if (wid < 8) {
                kredr(sred, u, lane, r);
                const float4 pa = ldcg4f(&g_r1[wp][pi]);
                float v0 = tanhf(r[0] + pa.x + bias0), v1 = tanhf(r[1] + pa.y + bias1);
                float v2 = tanhf(r[2] + pa.z + bias0), v3 = tanhf(r[3] + pa.w + bias1);
                u64 hi, lo; pack_hilo(v0, v1, v2, v3, hi, lo);
                stcg64(&g_h2hi[wp][ei], hi);
                stcg64(&g_h2lo[wp][ei], lo);
                float* ot = out + (size_t)t * BATCH * HD;
                *(float2*)&ot[(size_t)m0*HD + n0]     = make_float2(v0, v1);
                *(float2*)&ot[(size_t)(m0+8)*HD + n0] = make_float2(v2, v3);
                if (write_final && t == SEQ - 1) {
                    float* hf = out + OUT_MAIN + (size_t)BATCH*HD;
                    *(float2*)&hf[(size_t)m0*HD + n0]     = make_float2(v0, v1);
                    *(float2*)&hf[(size_t)(m0+8)*HD + n0] = make_float2(v2, v3);
                }
            }
            grid_arrive(&g_c2);                      // publish h2(t)
        }
    }
}

// ---------------------------------------------------------------------------
extern "C" void kernel_launch(void* const* d_in, const int* in_sizes, int n_in,
                              void* d_out, int out_size) {
    const float* x   = (const float*)d_in[0];
    const float* Wi0 = (const float*)d_in[1];
    const float* bi0 = (const float*)d_in[2];
    const float* Wh0 = (const float*)d_in[3];
    const float* bh0 = (const float*)d_in[4];
    const float* Wi1 = (const float*)d_in[5];
    const float* bi1 = (const float*)d_in[6];
    const float* Wh1 = (const float*)d_in[7];
    const float* bh1 = (const float*)d_in[8];
    float* out = (float*)d_out;

    const int write_final =
        ((size_t)out_size >= OUT_MAIN + (size_t)2 * BATCH * HD) ? 1 : 0;

    cudaFuncSetAttribute(rnn_recurrent_kernel,
                         cudaFuncAttributeMaxDynamicSharedMemorySize, SMEM2_BYTES);
    cudaFuncSetAttribute(rnn_precompute_mma,
                         cudaFuncAttributeMaxDynamicSharedMemorySize, PC_SMEM);

    rnn_reset_kernel<<<256, 256>>>();
    rnn_prepw_kernel<<<(4*GW_ENT + 255)/256, 256>>>(Wh0, Wi1, Wh1, Wi0);
    rnn_xpack_kernel<<<(GX_ENT + 255)/256, 256>>>(x);
    rnn_precompute_mma<<<dim3(16, 256), 256, PC_SMEM>>>(bi0, bh0);
    rnn_recurrent_kernel<<<2*NG, TPB, SMEM2_BYTES>>>(bi1, bh1, out, write_final);
}